// round 9
// baseline (speedup 1.0000x reference)
#include <cuda_runtime.h>
#include <cuda_bf16.h>
#include <cstdint>

#define DIMN 1024
#define NH   16
#define DH   64
#define NB   4
#define SXX  1024
#define SKK  2048   // Sx + Sy

// ---- scratch ----
// int8 quantized activations (x rows 0..4095, y rows 4096..8191) and weights
__device__ int8_t g_a1[8388608], g_a2[8388608];
__device__ float  g_sa[8192];
__device__ int8_t g_w1[5242880], g_w2[5242880];   // slots Qx,Kx,Vx,Ky,Vy
__device__ float  g_sw[5120];
// bf16 hi/lo for out-projection weight
__device__ __nv_bfloat16 g_Wh[1048576], g_Wl[1048576];
__device__ float g_bias[6144];                     // Qx,Kx,Vx,Ky,Vy,out
__device__ __nv_bfloat16 g_Qh[4194304],  g_Ql[4194304];   // [b,h,s,d]
__device__ __nv_bfloat16 g_Kh[8388608],  g_Kl[8388608];   // [b,h,s,d]
__device__ __nv_bfloat16 g_Vth[8388608], g_Vtl[8388608];  // [b,h,d,s]
__device__ __nv_bfloat16 g_Oh[4194304],  g_Ol[4194304];   // [b,s,dim]

// ============================================================================
// helpers (sm_80-era PTX only — ptxas target is plain sm_103)
// ============================================================================
__device__ __forceinline__ void cp16(uint32_t s, const void* g) {
    asm volatile("cp.async.cg.shared.global [%0], [%1], 16;"
                 :: "r"(s), "l"(__cvta_generic_to_global(g)) : "memory");
}
__device__ __forceinline__ void ldsm_x4(uint32_t& r0, uint32_t& r1,
                                        uint32_t& r2, uint32_t& r3, uint32_t a) {
    asm volatile("ldmatrix.sync.aligned.m8n8.x4.shared.b16 {%0,%1,%2,%3}, [%4];"
                 : "=r"(r0), "=r"(r1), "=r"(r2), "=r"(r3) : "r"(a));
}
__device__ __forceinline__ void mma_bf16(float* c, const uint32_t* a, const uint32_t* b) {
    asm volatile(
        "mma.sync.aligned.m16n8k16.row.col.f32.bf16.bf16.f32 "
        "{%0,%1,%2,%3}, {%4,%5,%6,%7}, {%8,%9}, {%0,%1,%2,%3};"
        : "+f"(c[0]), "+f"(c[1]), "+f"(c[2]), "+f"(c[3])
        : "r"(a[0]), "r"(a[1]), "r"(a[2]), "r"(a[3]), "r"(b[0]), "r"(b[1]));
}
__device__ __forceinline__ void mma_s8(int* c, const uint32_t* a, const uint32_t* b) {
    asm volatile(
        "mma.sync.aligned.m16n8k32.row.col.s32.s8.s8.s32 "
        "{%0,%1,%2,%3}, {%4,%5,%6,%7}, {%8,%9}, {%0,%1,%2,%3};"
        : "+r"(c[0]), "+r"(c[1]), "+r"(c[2]), "+r"(c[3])
        : "r"(a[0]), "r"(a[1]), "r"(a[2]), "r"(a[3]), "r"(b[0]), "r"(b[1]));
}
__device__ __forceinline__ uint32_t pack_bf16(float v0, float v1) {
    uint32_t r;
    asm("cvt.rn.bf16x2.f32 %0, %1, %2;" : "=r"(r) : "f"(v1), "f"(v0));
    return r;
}

// ============================================================================
// quantize: per-row two-word int8 (a = s*(128*a1 + a2), |a2|<=64)
// ============================================================================
__device__ __forceinline__ void quant1(float v, float inv, signed char& c1, signed char& c2) {
    float q = fminf(fmaxf(v * inv, -16256.f), 16256.f);
    float q1 = rintf(q * 0.0078125f);      // /128, in [-127,127]
    float q2 = rintf(q - 128.f * q1);      // in [-64,64]
    c1 = (signed char)(int)q1;
    c2 = (signed char)(int)q2;
}

__device__ __forceinline__ float rowmax_reduce(float mx, int tid) {
    __shared__ float red[8];
#pragma unroll
    for (int o = 16; o; o >>= 1) mx = fmaxf(mx, __shfl_xor_sync(0xffffffffu, mx, o));
    if ((tid & 31) == 0) red[tid >> 5] = mx;
    __syncthreads();
    return fmaxf(fmaxf(fmaxf(red[0], red[1]), fmaxf(red[2], red[3])),
                 fmaxf(fmaxf(red[4], red[5]), fmaxf(red[6], red[7])));
}

__global__ void __launch_bounds__(256)
actquant(const float* __restrict__ x, const float* __restrict__ y,
         int8_t* __restrict__ a1, int8_t* __restrict__ a2, float* __restrict__ sa)
{
    const int row = blockIdx.x;   // 0..8191
    const int tid = threadIdx.x;
    const float* src = (row < 4096) ? x + (size_t)row * 1024
                                    : y + (size_t)(row - 4096) * 1024;
    float4 v = ((const float4*)src)[tid];
    float mx = fmaxf(fmaxf(fabsf(v.x), fabsf(v.y)), fmaxf(fabsf(v.z), fabsf(v.w)));
    float rmax = rowmax_reduce(mx, tid);
    float s = (rmax > 1e-30f) ? rmax * (1.f / 16256.f) : 1.f;
    float inv = 1.f / s;
    char4 c1, c2;
    quant1(v.x, inv, c1.x, c2.x); quant1(v.y, inv, c1.y, c2.y);
    quant1(v.z, inv, c1.z, c2.z); quant1(v.w, inv, c1.w, c2.w);
    ((char4*)a1)[(size_t)row * 256 + tid] = c1;
    ((char4*)a2)[(size_t)row * 256 + tid] = c2;
    if (tid == 0) sa[row] = s;
}

__global__ void __launch_bounds__(256)
wquant(const float* w0, const float* w1p, const float* w2p,
       const float* w3, const float* w4,
       int8_t* __restrict__ a1, int8_t* __restrict__ a2, float* __restrict__ sw)
{
    const int row = blockIdx.x;   // 0..5119
    const int tid = threadIdx.x;
    const int slot = row >> 10, j = row & 1023;
    const float* base = (slot == 0) ? w0 : (slot == 1) ? w1p : (slot == 2) ? w2p
                      : (slot == 3) ? w3 : w4;
    const float* src = base + (size_t)j * 1024;
    float4 v = ((const float4*)src)[tid];
    float mx = fmaxf(fmaxf(fabsf(v.x), fabsf(v.y)), fmaxf(fabsf(v.z), fabsf(v.w)));
    float rmax = rowmax_reduce(mx, tid);
    float s = (rmax > 1e-30f) ? rmax * (1.f / 16256.f) : 1.f;
    float inv = 1.f / s;
    char4 c1, c2;
    quant1(v.x, inv, c1.x, c2.x); quant1(v.y, inv, c1.y, c2.y);
    quant1(v.z, inv, c1.z, c2.z); quant1(v.w, inv, c1.w, c2.w);
    ((char4*)a1)[(size_t)row * 256 + tid] = c1;
    ((char4*)a2)[(size_t)row * 256 + tid] = c2;
    if (tid == 0) sw[row] = s;
}

// ============================================================================
// W_out bf16 split + bias concat
// ============================================================================
__device__ __forceinline__ void split4(float4 v, __nv_bfloat16* hi, __nv_bfloat16* lo,
                                       size_t i2) {
    __nv_bfloat16 h0 = __float2bfloat16(v.x), h1 = __float2bfloat16(v.y);
    __nv_bfloat16 h2 = __float2bfloat16(v.z), h3 = __float2bfloat16(v.w);
    __nv_bfloat16 l0 = __float2bfloat16(v.x - __bfloat162float(h0));
    __nv_bfloat16 l1 = __float2bfloat16(v.y - __bfloat162float(h1));
    __nv_bfloat16 l2 = __float2bfloat16(v.z - __bfloat162float(h2));
    __nv_bfloat16 l3 = __float2bfloat16(v.w - __bfloat162float(h3));
    ((__nv_bfloat162*)hi)[i2]     = __halves2bfloat162(h0, h1);
    ((__nv_bfloat162*)hi)[i2 + 1] = __halves2bfloat162(h2, h3);
    ((__nv_bfloat162*)lo)[i2]     = __halves2bfloat162(l0, l1);
    ((__nv_bfloat162*)lo)[i2 + 1] = __halves2bfloat162(l2, l3);
}

__global__ void __launch_bounds__(256)
splitW5(const float* __restrict__ Wout,
        const float* b0, const float* b1, const float* b2,
        const float* b3, const float* b4, const float* b5,
        __nv_bfloat16* __restrict__ hi, __nv_bfloat16* __restrict__ lo,
        float* __restrict__ biasC)
{
    if (blockIdx.x >= 1024) {
        int i = (blockIdx.x - 1024) * 256 + threadIdx.x;   // 0..6143
        int slot = i >> 10, j = i & 1023;
        const float* src = (slot == 0) ? b0 : (slot == 1) ? b1 : (slot == 2) ? b2
                         : (slot == 3) ? b3 : (slot == 4) ? b4 : b5;
        biasC[i] = src[j];
        return;
    }
    int i = blockIdx.x * 256 + threadIdx.x;   // 0..262143
    split4(((const float4*)Wout)[i], hi, lo, 2 * (size_t)i);
}

// ============================================================================
// int8 projection GEMM: 128(M) x 128(N) x 1024, 512 threads, warp tile 32x32
// 3 IMMAs per k32 (a1b1 -> acc1; a1b2 + a2b1 -> accm)
// ============================================================================
#define TI8      10240                       // 128 rows x 80B pitch
#define STG_I8   (4 * TI8)                   // a1,a2,b1,b2
#define I8_SMEM  (3 * STG_I8)                // 122880

__device__ __forceinline__ void load_stage_i8(
    uint32_t sbase,
    const int8_t* __restrict__ A1, const int8_t* __restrict__ A2,
    const int8_t* __restrict__ B1, const int8_t* __restrict__ B2,
    int mBase, int nBase, int k0, int tid)
{
#pragma unroll
    for (int j = 0; j < 4; ++j) {
        const int idx = j * 512 + tid;   // 0..2047
        const int t = idx >> 9;
        const int q = idx & 511;
        const int r = q >> 2, c = q & 3;
        const int8_t* src = (t == 0) ? A1 : (t == 1) ? A2 : (t == 2) ? B1 : B2;
        const int base = (t < 2) ? mBase : nBase;
        cp16(sbase + t * TI8 + r * 80 + c * 16,
             src + (size_t)(base + r) * 1024 + k0 + c * 16);
    }
}

__global__ void __launch_bounds__(512, 1)
proj_i8(const int8_t* __restrict__ A1, const int8_t* __restrict__ A2,
        const float* __restrict__ saP,
        const int8_t* __restrict__ B1, const int8_t* __restrict__ B2,
        const float* __restrict__ sbP, const float* __restrict__ biasP,
        __nv_bfloat16* __restrict__ Qh, __nv_bfloat16* __restrict__ Ql,
        __nv_bfloat16* __restrict__ Kh, __nv_bfloat16* __restrict__ Kl,
        __nv_bfloat16* __restrict__ Vh, __nv_bfloat16* __restrict__ Vl,
        int is_y)
{
    extern __shared__ __align__(128) char smem[];
    const uint32_t sb = (uint32_t)__cvta_generic_to_shared(smem);
    const int tid = threadIdx.x, wid = tid >> 5, lid = tid & 31;
    const int mBase = blockIdx.y * 128;
    const int nBase = blockIdx.x * 128;
    const int wm = (wid >> 2) * 32;
    const int wn = (wid & 3) * 32;
    // ldmatrix addressing (byte units)
    const int aRow = lid & 15, aColB = (lid >> 4) * 16;
    const int bRow = ((lid >> 4) & 1) * 8 + (lid & 7);
    const int bColB = ((lid >> 3) & 1) * 16;

    int acc1[2][4][4], accm[2][4][4];
#pragma unroll
    for (int mt = 0; mt < 2; mt++)
#pragma unroll
        for (int nt = 0; nt < 4; nt++)
#pragma unroll
            for (int e = 0; e < 4; e++) { acc1[mt][nt][e] = 0; accm[mt][nt][e] = 0; }

    load_stage_i8(sb, A1, A2, B1, B2, mBase, nBase, 0, tid);
    asm volatile("cp.async.commit_group;" ::: "memory");
    load_stage_i8(sb + STG_I8, A1, A2, B1, B2, mBase, nBase, 64, tid);
    asm volatile("cp.async.commit_group;" ::: "memory");

    for (int i = 0; i < 16; ++i) {
        if (i + 1 < 16) asm volatile("cp.async.wait_group 1;" ::: "memory");
        else            asm volatile("cp.async.wait_group 0;" ::: "memory");
        __syncthreads();
        if (i + 2 < 16) {
            load_stage_i8(sb + ((i + 2) % 3) * STG_I8, A1, A2, B1, B2,
                          mBase, nBase, (i + 2) * 64, tid);
            asm volatile("cp.async.commit_group;" ::: "memory");
        }
        const uint32_t st = sb + (i % 3) * STG_I8;

#pragma unroll
        for (int kk = 0; kk < 64; kk += 32) {
            uint32_t a1f[2][4], a2f[2][4];
#pragma unroll
            for (int mt = 0; mt < 2; mt++) {
                const uint32_t ao = (wm + mt * 16 + aRow) * 80 + kk + aColB;
                ldsm_x4(a1f[mt][0], a1f[mt][1], a1f[mt][2], a1f[mt][3], st + ao);
                ldsm_x4(a2f[mt][0], a2f[mt][1], a2f[mt][2], a2f[mt][3], st + TI8 + ao);
            }
#pragma unroll
            for (int ntp = 0; ntp < 2; ntp++) {
                const uint32_t bo = (wn + ntp * 16 + bRow) * 80 + kk + bColB;
                uint32_t b1f[4], b2f[4];
                ldsm_x4(b1f[0], b1f[1], b1f[2], b1f[3], st + 2 * TI8 + bo);
                ldsm_x4(b2f[0], b2f[1], b2f[2], b2f[3], st + 3 * TI8 + bo);
#pragma unroll
                for (int mt = 0; mt < 2; mt++) {
                    mma_s8(acc1[mt][2 * ntp],     a1f[mt], &b1f[0]);
                    mma_s8(accm[mt][2 * ntp],     a1f[mt], &b2f[0]);
                    mma_s8(accm[mt][2 * ntp],     a2f[mt], &b1f[0]);
                    mma_s8(acc1[mt][2 * ntp + 1], a1f[mt], &b1f[2]);
                    mma_s8(accm[mt][2 * ntp + 1], a1f[mt], &b2f[2]);
                    mma_s8(accm[mt][2 * ntp + 1], a2f[mt], &b1f[2]);
                }
            }
        }
    }

    // epilogue: D = sa*sb*(16384*acc1 + 128*accm); (D + bias) * typeScale
    const int lr = lid >> 2, lc = (lid & 3) * 2;
    const int type0 = ((nBase + wn) >> 10) + is_y;      // 0=Q 1=K 2=V
    const float scale = (type0 == 0) ? 0.125f : 1.f;
    __nv_bfloat16 *oH, *oL;
    int Sst, mode;
    if (type0 == 0)      { oH = Qh; oL = Ql; Sst = SXX; mode = 1; }
    else if (type0 == 1) { oH = Kh; oL = Kl; Sst = SKK; mode = 1; }
    else                 { oH = Vh; oL = Vl; Sst = SKK; mode = 2; }
    const int seq_off = is_y ? SXX : 0;

#pragma unroll
    for (int mt = 0; mt < 2; mt++) {
#pragma unroll
        for (int half = 0; half < 2; half++) {
            const int m  = mBase + wm + mt * 16 + half * 8 + lr;
            const float sam = saP[m];
            const int bb = m >> 10, sdx = m & 1023;
#pragma unroll
            for (int nt = 0; nt < 4; nt++) {
                const int n = nBase + wn + nt * 8 + lc;
                const float d0 = (float)acc1[mt][nt][half * 2 + 0] * 16384.f
                               + (float)accm[mt][nt][half * 2 + 0] * 128.f;
                const float d1 = (float)acc1[mt][nt][half * 2 + 1] * 16384.f
                               + (float)accm[mt][nt][half * 2 + 1] * 128.f;
                const float v0 = (d0 * (sam * sbP[n])     + biasP[n])     * scale;
                const float v1 = (d1 * (sam * sbP[n + 1]) + biasP[n + 1]) * scale;
                const __nv_bfloat16 h0 = __float2bfloat16(v0);
                const __nv_bfloat16 l0 = __float2bfloat16(v0 - __bfloat162float(h0));
                const __nv_bfloat16 h1 = __float2bfloat16(v1);
                const __nv_bfloat16 l1 = __float2bfloat16(v1 - __bfloat162float(h1));
                const int ncol = n & 1023;
                const int hh = ncol >> 6, d = ncol & 63;
                if (mode == 1) {
                    size_t idx = (((size_t)(bb * NH + hh)) * Sst + seq_off + sdx) * DH + d;
                    *(__nv_bfloat162*)&oH[idx] = __halves2bfloat162(h0, h1);
                    *(__nv_bfloat162*)&oL[idx] = __halves2bfloat162(l0, l1);
                } else {
                    size_t idx = (((size_t)(bb * NH + hh)) * DH + d) * (size_t)Sst
                               + seq_off + sdx;
                    oH[idx] = h0; oL[idx] = l0;
                    oH[idx + Sst] = h1; oL[idx + Sst] = l1;
                }
            }
        }
    }
}

// ============================================================================
// bf16 hi/lo 128x256 mainloop (out-projection only) — unchanged from R8
// ============================================================================
#define PITCH    40
#define AREG_B   (128 * PITCH * 2)
#define BREG_B   (256 * PITCH * 2)
#define STAGE_B  (2 * AREG_B + 2 * BREG_B)
#define GEMM_SMEM (3 * STAGE_B)

__device__ __forceinline__ void load_stage(
    uint32_t sbase,
    const __nv_bfloat16* __restrict__ Ah, const __nv_bfloat16* __restrict__ Al,
    const __nv_bfloat16* __restrict__ Bh, const __nv_bfloat16* __restrict__ Bl,
    int mBase, int nBase, int k0, int tid)
{
#pragma unroll
    for (int j = 0; j < 6; ++j) {
        const int idx = j * 512 + tid;
        const int c = idx & 3;
        if (idx < 1024) {
            const int r = (idx & 511) >> 2;
            const __nv_bfloat16* src = (idx < 512) ? Ah : Al;
            const uint32_t dst = sbase + ((idx < 512) ? 0 : AREG_B);
            cp16(dst + r * (PITCH * 2) + c * 16,
                 src + (size_t)(mBase + r) * 1024 + k0 + c * 8);
        } else {
            const int q = idx - 1024;
            const int r = (q & 1023) >> 2;
            const __nv_bfloat16* src = (q < 1024) ? Bh : Bl;
            const uint32_t dst = sbase + 2 * AREG_B + ((q < 1024) ? 0 : BREG_B);
            cp16(dst + r * (PITCH * 2) + c * 16,
                 src + (size_t)(nBase + r) * 1024 + k0 + c * 8);
        }
    }
}

__global__ void __launch_bounds__(512, 1)
gemm_out(const __nv_bfloat16* __restrict__ Ah, const __nv_bfloat16* __restrict__ Al,
         const __nv_bfloat16* __restrict__ Wh, const __nv_bfloat16* __restrict__ Wl,
         const float* __restrict__ bias, float* __restrict__ outF)
{
    extern __shared__ __align__(128) char smem[];
    const uint32_t sb = (uint32_t)__cvta_generic_to_shared(smem);
    const int tid = threadIdx.x, wid = tid >> 5, lid = tid & 31;
    const int mBase = blockIdx.y * 128;
    const int nBase = blockIdx.x * 256;
    const int wm = (wid >> 2) * 32;
    const int wn = (wid & 3) * 64;
    const int aRow = lid & 15, aCol = (lid >> 4) * 8;
    const int bRow = ((lid >> 4) & 1) * 8 + (lid & 7);
    const int bCol = ((lid >> 3) & 1) * 8;

    float acc[2][8][4];
#pragma unroll
    for (int mt = 0; mt < 2; mt++)
#pragma unroll
        for (int nt = 0; nt < 8; nt++)
#pragma unroll
            for (int e = 0; e < 4; e++) acc[mt][nt][e] = 0.f;

    load_stage(sb, Ah, Al, Wh, Wl, mBase, nBase, 0, tid);
    asm volatile("cp.async.commit_group;" ::: "memory");
    load_stage(sb + STAGE_B, Ah, Al, Wh, Wl, mBase, nBase, 32, tid);
    asm volatile("cp.async.commit_group;" ::: "memory");

    for (int i = 0; i < 32; ++i) {
        if (i + 1 < 32) asm volatile("cp.async.wait_group 1;" ::: "memory");
        else            asm volatile("cp.async.wait_group 0;" ::: "memory");
        __syncthreads();
        if (i + 2 < 32) {
            load_stage(sb + ((i + 2) % 3) * STAGE_B, Ah, Al, Wh, Wl,
                       mBase, nBase, (i + 2) * 32, tid);
            asm volatile("cp.async.commit_group;" ::: "memory");
        }
        const uint32_t st = sb + (i % 3) * STAGE_B;
        const uint32_t sAh = st, sAl = st + AREG_B;
        const uint32_t sBh = st + 2 * AREG_B, sBl = sBh + BREG_B;

#pragma unroll
        for (int kk = 0; kk < 32; kk += 16) {
            uint32_t ah[2][4], al[2][4];
#pragma unroll
            for (int mt = 0; mt < 2; mt++) {
                const uint32_t ao = (wm + mt * 16 + aRow) * (PITCH * 2) + (kk + aCol) * 2;
                ldsm_x4(ah[mt][0], ah[mt][1], ah[mt][2], ah[mt][3], sAh + ao);
                ldsm_x4(al[mt][0], al[mt][1], al[mt][2], al[mt][3], sAl + ao);
            }
#pragma unroll
            for (int ntp = 0; ntp < 4; ntp++) {
                const uint32_t bo = (wn + ntp * 16 + bRow) * (PITCH * 2) + (kk + bCol) * 2;
                uint32_t bh4[4], bl4[4];
                ldsm_x4(bh4[0], bh4[1], bh4[2], bh4[3], sBh + bo);
                ldsm_x4(bl4[0], bl4[1], bl4[2], bl4[3], sBl + bo);
#pragma unroll
                for (int mt = 0; mt < 2; mt++) {
                    mma_bf16(acc[mt][2 * ntp],     ah[mt], &bh4[0]);
                    mma_bf16(acc[mt][2 * ntp],     al[mt], &bh4[0]);
                    mma_bf16(acc[mt][2 * ntp],     ah[mt], &bl4[0]);
                    mma_bf16(acc[mt][2 * ntp + 1], ah[mt], &bh4[2]);
                    mma_bf16(acc[mt][2 * ntp + 1], al[mt], &bh4[2]);
                    mma_bf16(acc[mt][2 * ntp + 1], ah[mt], &bl4[2]);
                }
            }
        }
    }

    const int lr = lid >> 2, lc = (lid & 3) * 2;
#pragma unroll
    for (int mt = 0; mt < 2; mt++)
#pragma unroll
        for (int half = 0; half < 2; half++) {
            const int m = mBase + wm + mt * 16 + half * 8 + lr;
#pragma unroll
            for (int nt = 0; nt < 8; nt++) {
                const int n = nBase + wn + nt * 8 + lc;
                *(float2*)&outF[(size_t)m * DIMN + n] = make_float2(
                    acc[mt][nt][half * 2 + 0] + bias[n],
                    acc[mt][nt][half * 2 + 1] + bias[n + 1]);
            }
        }
}

// ============================================================================
// tensor-core flash attention (unchanged from R8)
// ============================================================================
#define APITCH   72
#define ATILE_B  (64 * APITCH * 2)
#define ASTAGE_B (4 * ATILE_B)
#define ATTN_SMEM (3 * ASTAGE_B)

__device__ __forceinline__ void load_kv(
    uint32_t dst,
    const __nv_bfloat16* __restrict__ Kh_g, const __nv_bfloat16* __restrict__ Kl_g,
    const __nv_bfloat16* __restrict__ Vh_g, const __nv_bfloat16* __restrict__ Vl_g,
    int kt, int tid)
{
#pragma unroll
    for (int j = 0; j < 8; ++j) {
        const int t = j >> 1;
        const int q = (j & 1) * 256 + tid;
        const int r = q >> 3, c = q & 7;
        const uint32_t da = dst + t * ATILE_B + r * (APITCH * 2) + c * 16;
        if (t == 0)      cp16(da, Kh_g + (size_t)(kt * 64 + r) * 64 + c * 8);
        else if (t == 1) cp16(da, Kl_g + (size_t)(kt * 64 + r) * 64 + c * 8);
        else if (t == 2) cp16(da, Vh_g + (size_t)r * SKK + kt * 64 + c * 8);
        else             cp16(da, Vl_g + (size_t)r * SKK + kt * 64 + c * 8);
    }
}

__global__ void __launch_bounds__(256, 1)
attn_tc(const __nv_bfloat16* __restrict__ Qh, const __nv_bfloat16* __restrict__ Ql,
        const __nv_bfloat16* __restrict__ Kh, const __nv_bfloat16* __restrict__ Kl,
        const __nv_bfloat16* __restrict__ Vth, const __nv_bfloat16* __restrict__ Vtl,
        __nv_bfloat16* __restrict__ Oh, __nv_bfloat16* __restrict__ Ol)
{
    extern __shared__ __align__(128) char smem[];
    const uint32_t sb = (uint32_t)__cvta_generic_to_shared(smem);
    const int tid = threadIdx.x, wid = tid >> 5, lid = tid & 31;
    const int qt = blockIdx.x, h = blockIdx.y, b = blockIdx.z;

    const __nv_bfloat16* Qgh = Qh + ((size_t)(b * NH + h) * SXX + qt * 128) * DH;
    const __nv_bfloat16* Qgl = Ql + ((size_t)(b * NH + h) * SXX + qt * 128) * DH;
    const __nv_bfloat16* Kgh = Kh + (size_t)(b * NH + h) * SKK * DH;
    const __nv_bfloat16* Kgl = Kl + (size_t)(b * NH + h) * SKK * DH;
    const __nv_bfloat16* Vgh = Vth + (size_t)(b * NH + h) * DH * SKK;
    const __nv_bfloat16* Vgl = Vtl + (size_t)(b * NH + h) * DH * SKK;

    load_kv(sb, Kgh, Kgl, Vgh, Vgl, 0, tid);
    asm volatile("cp.async.commit_group;" ::: "memory");
    load_kv(sb + ASTAGE_B, Kgh, Kgl, Vgh, Vgl, 1, tid);
    asm volatile("cp.async.commit_group;" ::: "memory");
#pragma unroll
    for (int j = 0; j < 4; ++j) {
        const int q = j * 256 + tid;
        const int r = q >> 3, c = q & 7;
        cp16(sb + 2 * ASTAGE_B + r * (APITCH * 2) + c * 16, Qgh + (size_t)r * 64 + c * 8);
        cp16(sb + 2 * ASTAGE_B + 18432 + r * (APITCH * 2) + c * 16,
             Qgl + (size_t)r * 64 + c * 8);
    }
    asm volatile("cp.async.commit_group;" ::: "memory");
    asm volatile("cp.async.wait_group 0;" ::: "memory");
    __syncthreads();

    uint32_t qhf[4][4], qlf[4][4];
    const int aRow = lid & 15, aCol = (lid >> 4) * 8;
#pragma unroll
    for (int kd = 0; kd < 4; kd++) {
        const uint32_t ao = (wid * 16 + aRow) * (APITCH * 2) + (kd * 16 + aCol) * 2;
        ldsm_x4(qhf[kd][0], qhf[kd][1], qhf[kd][2], qhf[kd][3], sb + 2 * ASTAGE_B + ao);
        ldsm_x4(qlf[kd][0], qlf[kd][1], qlf[kd][2], qlf[kd][3],
                sb + 2 * ASTAGE_B + 18432 + ao);
    }

    float m0 = -1e30f, m1 = -1e30f, l0 = 0.f, l1 = 0.f;
    float oacc[8][4];
#pragma unroll
    for (int dt = 0; dt < 8; dt++)
#pragma unroll
        for (int e = 0; e < 4; e++) oacc[dt][e] = 0.f;

    const int bRow = ((lid >> 4) & 1) * 8 + (lid & 7);
    const int bCol = ((lid >> 3) & 1) * 8;

#pragma unroll 1
    for (int kt = 0; kt < 32; ++kt) {
        if (kt + 1 < 32) asm volatile("cp.async.wait_group 1;" ::: "memory");
        else             asm volatile("cp.async.wait_group 0;" ::: "memory");
        __syncthreads();
        if (kt + 2 < 32) {
            load_kv(sb + ((kt + 2) % 3) * ASTAGE_B, Kgh, Kgl, Vgh, Vgl, kt + 2, tid);
            asm volatile("cp.async.commit_group;" ::: "memory");
        }
        const uint32_t st = sb + (kt % 3) * ASTAGE_B;

        float sc[8][4];
#pragma unroll
        for (int nt = 0; nt < 8; nt++)
#pragma unroll
            for (int e = 0; e < 4; e++) sc[nt][e] = 0.f;
#pragma unroll
        for (int kd = 0; kd < 4; kd++) {
#pragma unroll
            for (int ntp = 0; ntp < 4; ntp++) {
                const uint32_t bo = (ntp * 16 + bRow) * (APITCH * 2) + (kd * 16 + bCol) * 2;
                uint32_t kh4[4], kl4[4];
                ldsm_x4(kh4[0], kh4[1], kh4[2], kh4[3], st + bo);
                ldsm_x4(kl4[0], kl4[1], kl4[2], kl4[3], st + ATILE_B + bo);
                mma_bf16(sc[2 * ntp],     qhf[kd], &kh4[0]);
                mma_bf16(sc[2 * ntp],     qlf[kd], &kh4[0]);
                mma_bf16(sc[2 * ntp],     qhf[kd], &kl4[0]);
                mma_bf16(sc[2 * ntp + 1], qhf[kd], &kh4[2]);
                mma_bf16(sc[2 * ntp + 1], qlf[kd], &kh4[2]);
                mma_bf16(sc[2 * ntp + 1], qhf[kd], &kl4[2]);
            }
        }

        float mx0 = -1e30f, mx1 = -1e30f;
#pragma unroll
        for (int nt = 0; nt < 8; nt++) {
            mx0 = fmaxf(mx0, fmaxf(sc[nt][0], sc[nt][1]));
            mx1 = fmaxf(mx1, fmaxf(sc[nt][2], sc[nt][3]));
        }
        mx0 = fmaxf(mx0, __shfl_xor_sync(0xffffffffu, mx0, 1));
        mx0 = fmaxf(mx0, __shfl_xor_sync(0xffffffffu, mx0, 2));
        mx1 = fmaxf(mx1, __shfl_xor_sync(0xffffffffu, mx1, 1));
        mx1 = fmaxf(mx1, __shfl_xor_sync(0xffffffffu, mx1, 2));
        const float mn0 = fmaxf(m0, mx0), mn1 = fmaxf(m1, mx1);
        const float al0 = __expf(m0 - mn0), al1 = __expf(m1 - mn1);
        m0 = mn0; m1 = mn1;
        float rs0 = 0.f, rs1 = 0.f;
#pragma unroll
        for (int nt = 0; nt < 8; nt++) {
            sc[nt][0] = __expf(sc[nt][0] - m0);
            sc[nt][1] = __expf(sc[nt][1] - m0);
            sc[nt][2] = __expf(sc[nt][2] - m1);
            sc[nt][3] = __expf(sc[nt][3] - m1);
            rs0 += sc[nt][0] + sc[nt][1];
            rs1 += sc[nt][2] + sc[nt][3];
        }
        rs0 += __shfl_xor_sync(0xffffffffu, rs0, 1);
        rs0 += __shfl_xor_sync(0xffffffffu, rs0, 2);
        rs1 += __shfl_xor_sync(0xffffffffu, rs1, 1);
        rs1 += __shfl_xor_sync(0xffffffffu, rs1, 2);
        l0 = l0 * al0 + rs0;
        l1 = l1 * al1 + rs1;
#pragma unroll
        for (int dt = 0; dt < 8; dt++) {
            oacc[dt][0] *= al0; oacc[dt][1] *= al0;
            oacc[dt][2] *= al1; oacc[dt][3] *= al1;
        }

#pragma unroll
        for (int ks = 0; ks < 4; ks++) {
            float p0 = sc[2 * ks][0],     p1 = sc[2 * ks][1];
            float p2 = sc[2 * ks][2],     p3 = sc[2 * ks][3];
            float p4 = sc[2 * ks + 1][0], p5 = sc[2 * ks + 1][1];
            float p6 = sc[2 * ks + 1][2], p7 = sc[2 * ks + 1][3];
            uint32_t pha[4], pla[4];
            pha[0] = pack_bf16(p0, p1); pha[1] = pack_bf16(p2, p3);
            pha[2] = pack_bf16(p4, p5); pha[3] = pack_bf16(p6, p7);
            pla[0] = pack_bf16(p0 - __bfloat162float(__float2bfloat16(p0)),
                               p1 - __bfloat162float(__float2bfloat16(p1)));
            pla[1] = pack_bf16(p2 - __bfloat162float(__float2bfloat16(p2)),
                               p3 - __bfloat162float(__float2bfloat16(p3)));
            pla[2] = pack_bf16(p4 - __bfloat162float(__float2bfloat16(p4)),
                               p5 - __bfloat162float(__float2bfloat16(p5)));
            pla[3] = pack_bf16(p6 - __bfloat162float(__float2bfloat16(p6)),
                               p7 - __bfloat162float(__float2bfloat16(p7)));
#pragma unroll
            for (int dtp = 0; dtp < 4; dtp++) {
                const uint32_t vo = (dtp * 16 + bRow) * (APITCH * 2) + (ks * 16 + bCol) * 2;
                uint32_t vh4[4], vl4[4];
                ldsm_x4(vh4[0], vh4[1], vh4[2], vh4[3], st + 2 * ATILE_B + vo);
                ldsm_x4(vl4[0], vl4[1], vl4[2], vl4[3], st + 3 * ATILE_B + vo);
                mma_bf16(oacc[2 * dtp],     pha, &vh4[0]);
                mma_bf16(oacc[2 * dtp],     pla, &vh4[0]);
                mma_bf16(oacc[2 * dtp],     pha, &vl4[0]);
                mma_bf16(oacc[2 * dtp + 1], pha, &vh4[2]);
                mma_bf16(oacc[2 * dtp + 1], pla, &vh4[2]);
                mma_bf16(oacc[2 * dtp + 1], pha, &vl4[2]);
            }
        }
    }

    const float inv0 = 1.f / l0, inv1 = 1.f / l1;
    const int row0 = qt * 128 + wid * 16 + (lid >> 2);
    const int row1 = row0 + 8;
    const int lc = (lid & 3) * 2;
#pragma unroll
    for (int dt = 0; dt < 8; dt++) {
        const int col = h * 64 + dt * 8 + lc;
        {
            const float v0 = oacc[dt][0] * inv0, v1 = oacc[dt][1] * inv0;
            const __nv_bfloat16 h0 = __float2bfloat16(v0);
            const __nv_bfloat16 e0 = __float2bfloat16(v0 - __bfloat162float(h0));
            const __nv_bfloat16 h1 = __float2bfloat16(v1);
            const __nv_bfloat16 e1 = __float2bfloat16(v1 - __bfloat162float(h1));
            const size_t i0 = ((size_t)b * SXX + row0) * DIMN + col;
            *(__nv_bfloat162*)&Oh[i0] = __halves2bfloat162(h0, h1);
            *(__nv_bfloat162*)&Ol[i0] = __halves2bfloat162(e0, e1);
        }
        {
            const float v0 = oacc[dt][2] * inv1, v1 = oacc[dt][3] * inv1;
            const __nv_bfloat16 h0 = __float2bfloat16(v0);
            const __nv_bfloat16 e0 = __float2bfloat16(v0 - __bfloat162float(h0));
            const __nv_bfloat16 h1 = __float2bfloat16(v1);
            const __nv_bfloat16 e1 = __float2bfloat16(v1 - __bfloat162float(h1));
            const size_t i1 = ((size_t)b * SXX + row1) * DIMN + col;
            *(__nv_bfloat162*)&Oh[i1] = __halves2bfloat162(h0, h1);
            *(__nv_bfloat162*)&Ol[i1] = __halves2bfloat162(e0, e1);
        }
    }
}

// ============================================================================
// launch
// ============================================================================
extern "C" void kernel_launch(void* const* d_in, const int* in_sizes, int n_in,
                              void* d_out, int out_size)
{
    const float* x     = (const float*)d_in[0];
    const float* y     = (const float*)d_in[1];
    const float* W_Kx  = (const float*)d_in[2];
    const float* b_Kx  = (const float*)d_in[3];
    const float* W_Qx  = (const float*)d_in[4];
    const float* b_Qx  = (const float*)d_in[5];
    const float* W_Vx  = (const float*)d_in[6];
    const float* b_Vx  = (const float*)d_in[7];
    const float* W_Ky  = (const float*)d_in[8];
    const float* b_Ky  = (const float*)d_in[9];
    const float* W_Vy  = (const float*)d_in[10];
    const float* b_Vy  = (const float*)d_in[11];
    const float* W_out = (const float*)d_in[12];
    const float* b_out = (const float*)d_in[13];
    float* out = (float*)d_out;

    int8_t *a1p, *a2p, *w1p, *w2p;
    float *sap, *swp, *biasC;
    __nv_bfloat16 *Wh, *Wl;
    __nv_bfloat16 *Qhp, *Qlp, *Khp, *Klp, *Vhp, *Vlp, *Ohp, *Olp;
    cudaGetSymbolAddress((void**)&a1p, g_a1);  cudaGetSymbolAddress((void**)&a2p, g_a2);
    cudaGetSymbolAddress((void**)&sap, g_sa);
    cudaGetSymbolAddress((void**)&w1p, g_w1);  cudaGetSymbolAddress((void**)&w2p, g_w2);
    cudaGetSymbolAddress((void**)&swp, g_sw);
    cudaGetSymbolAddress((void**)&Wh, g_Wh);   cudaGetSymbolAddress((void**)&Wl, g_Wl);
    cudaGetSymbolAddress((void**)&biasC, g_bias);
    cudaGetSymbolAddress((void**)&Qhp, g_Qh);  cudaGetSymbolAddress((void**)&Qlp, g_Ql);
    cudaGetSymbolAddress((void**)&Khp, g_Kh);  cudaGetSymbolAddress((void**)&Klp, g_Kl);
    cudaGetSymbolAddress((void**)&Vhp, g_Vth); cudaGetSymbolAddress((void**)&Vlp, g_Vtl);
    cudaGetSymbolAddress((void**)&Ohp, g_Oh);  cudaGetSymbolAddress((void**)&Olp, g_Ol);

    actquant<<<8192, 256>>>(x, y, a1p, a2p, sap);
    wquant<<<5120, 256>>>(W_Qx, W_Kx, W_Vx, W_Ky, W_Vy, w1p, w2p, swp);
    splitW5<<<1048, 256>>>(W_out, b_Qx, b_Kx, b_Vx, b_Ky, b_Vy, b_out,
                           Wh, Wl, biasC);

    cudaFuncSetAttribute(proj_i8,  cudaFuncAttributeMaxDynamicSharedMemorySize, I8_SMEM);
    cudaFuncSetAttribute(gemm_out, cudaFuncAttributeMaxDynamicSharedMemorySize, GEMM_SMEM);
    cudaFuncSetAttribute(attn_tc,  cudaFuncAttributeMaxDynamicSharedMemorySize, ATTN_SMEM);

    // x -> Q,K,V (N=3072), y -> Ky,Vy (N=2048)
    proj_i8<<<dim3(24, 32), 512, I8_SMEM>>>(a1p, a2p, sap,
                                            w1p, w2p, swp, biasC,
                                            Qhp, Qlp, Khp, Klp, Vhp, Vlp, 0);
    proj_i8<<<dim3(16, 32), 512, I8_SMEM>>>(a1p + 4194304ull, a2p + 4194304ull, sap + 4096,
                                            w1p + 3145728ull, w2p + 3145728ull, swp + 3072,
                                            biasC + 3072,
                                            Qhp, Qlp, Khp, Klp, Vhp, Vlp, 1);

    attn_tc<<<dim3(8, 16, 4), 256, ATTN_SMEM>>>(Qhp, Qlp, Khp, Klp, Vhp, Vlp, Ohp, Olp);

    gemm_out<<<dim3(4, 32), 512, GEMM_SMEM>>>(Ohp, Olp, Wh, Wl, b_out, out);
}

// round 10
// speedup vs baseline: 2.5366x; 2.5366x over previous
#include <cuda_runtime.h>
#include <cuda_fp16.h>
#include <cstdint>

#define DIMN 1024
#define NH   16
#define DH   64
#define NB   4
#define SXX  1024
#define SKK  2048   // Sx + Sy

// ---- scratch (fp16; A-side operands keep hi/lo, B-side single) ----
__device__ __half g_xh[4194304], g_xl[4194304];
__device__ __half g_yh[4194304], g_yl[4194304];
__device__ __half g_W[6 * 1048576];            // slots: Qx,Kx,Vx,Ky,Vy,out
__device__ float  g_bias[6144];
__device__ __half g_Qh[4194304], g_Ql[4194304];  // [b,h,s,d] hi/lo (A operand)
__device__ __half g_K[8388608];                  // [b,h,s,d]  single (B operand)
__device__ __half g_Vt[8388608];                 // [b,h,d,s]  single (B operand)
__device__ __half g_Oh[4194304], g_Ol[4194304];  // [b,s,dim] hi/lo

// ============================================================================
// helpers (sm_80-era PTX only — ptxas target is plain sm_103)
// ============================================================================
__device__ __forceinline__ void cp16(uint32_t s, const void* g) {
    asm volatile("cp.async.cg.shared.global [%0], [%1], 16;"
                 :: "r"(s), "l"(__cvta_generic_to_global(g)) : "memory");
}
__device__ __forceinline__ void ldsm_x4(uint32_t& r0, uint32_t& r1,
                                        uint32_t& r2, uint32_t& r3, uint32_t a) {
    asm volatile("ldmatrix.sync.aligned.m8n8.x4.shared.b16 {%0,%1,%2,%3}, [%4];"
                 : "=r"(r0), "=r"(r1), "=r"(r2), "=r"(r3) : "r"(a));
}
__device__ __forceinline__ void mma_f16(float* c, const uint32_t* a, const uint32_t* b) {
    asm volatile(
        "mma.sync.aligned.m16n8k16.row.col.f32.f16.f16.f32 "
        "{%0,%1,%2,%3}, {%4,%5,%6,%7}, {%8,%9}, {%0,%1,%2,%3};"
        : "+f"(c[0]), "+f"(c[1]), "+f"(c[2]), "+f"(c[3])
        : "r"(a[0]), "r"(a[1]), "r"(a[2]), "r"(a[3]), "r"(b[0]), "r"(b[1]));
}
__device__ __forceinline__ uint32_t pack_f16(float v0, float v1) {
    uint32_t r;
    asm("cvt.rn.f16x2.f32 %0, %1, %2;" : "=r"(r) : "f"(v1), "f"(v0));
    return r;
}

// ============================================================================
// converts
// ============================================================================
__device__ __forceinline__ void split4h(float4 v, __half* hi, __half* lo, size_t i2) {
    __half h0 = __float2half_rn(v.x), h1 = __float2half_rn(v.y);
    __half h2 = __float2half_rn(v.z), h3 = __float2half_rn(v.w);
    __half l0 = __float2half_rn(v.x - __half2float(h0));
    __half l1 = __float2half_rn(v.y - __half2float(h1));
    __half l2 = __float2half_rn(v.z - __half2float(h2));
    __half l3 = __float2half_rn(v.w - __half2float(h3));
    ((__half2*)hi)[i2]     = __halves2half2(h0, h1);
    ((__half2*)hi)[i2 + 1] = __halves2half2(h2, h3);
    ((__half2*)lo)[i2]     = __halves2half2(l0, l1);
    ((__half2*)lo)[i2 + 1] = __halves2half2(l2, l3);
}

// x and y -> fp16 hi/lo (grid 8192)
__global__ void __launch_bounds__(256)
splitxy_kernel(const float* __restrict__ x, const float* __restrict__ y,
               __half* __restrict__ xh, __half* __restrict__ xl,
               __half* __restrict__ yh, __half* __restrict__ yl)
{
    int i = blockIdx.x * 256 + threadIdx.x;
    if (i < 1048576) split4h(((const float4*)x)[i], xh, xl, 2 * (size_t)i);
    else {
        int j = i - 1048576;
        split4h(((const float4*)y)[j], yh, yl, 2 * (size_t)j);
    }
}

// all six weights -> single fp16, + bias concat (grid 6168)
__global__ void __launch_bounds__(256)
cvtW6(const float* s0, const float* s1, const float* s2,
      const float* s3, const float* s4, const float* s5,
      const float* b0, const float* b1, const float* b2,
      const float* b3, const float* b4, const float* b5,
      __half* __restrict__ W, float* __restrict__ biasC)
{
    if (blockIdx.x >= 6144) {
        int i = (blockIdx.x - 6144) * 256 + threadIdx.x;
        int slot = i >> 10, j = i & 1023;
        const float* src = (slot == 0) ? b0 : (slot == 1) ? b1 : (slot == 2) ? b2
                         : (slot == 3) ? b3 : (slot == 4) ? b4 : b5;
        biasC[i] = src[j];
        return;
    }
    int i = blockIdx.x * 256 + threadIdx.x;
    int slot = i >> 18, j = i & 262143;
    const float* src = (slot == 0) ? s0 : (slot == 1) ? s1 : (slot == 2) ? s2
                     : (slot == 3) ? s3 : (slot == 4) ? s4 : s5;
    float4 v = ((const float4*)src)[j];
    ((__half2*)W)[2 * (size_t)i]     = __halves2half2(__float2half_rn(v.x), __float2half_rn(v.y));
    ((__half2*)W)[2 * (size_t)i + 1] = __halves2half2(__float2half_rn(v.z), __float2half_rn(v.w));
}

// ============================================================================
// 128(M) x 256(N) x K=1024 mainloop: A fp16 hi/lo, B fp16 single, 2 MMAs/k16.
// 512 threads / 16 warps (4m x 4n), warp tile 32x64, 3-stage cp.async.
// stage: Ah(128x80B) + Al(128x80B) + B(256x80B) = 40960 B
// ============================================================================
#define PITCH    40
#define AREG_B   (128 * PITCH * 2)           // 10240
#define BREG_B   (256 * PITCH * 2)           // 20480
#define STAGE_B  (2 * AREG_B + BREG_B)       // 40960
#define GEMM_SMEM (3 * STAGE_B)              // 122880

__device__ __forceinline__ void load_stage(
    uint32_t sbase,
    const __half* __restrict__ Ah, const __half* __restrict__ Al,
    const __half* __restrict__ B,
    int mBase, int nBase, int k0, int tid)
{
    // 2048 chunks: 0..511 Ah, 512..1023 Al, 1024..2047 B
#pragma unroll
    for (int j = 0; j < 4; ++j) {
        const int idx = j * 512 + tid;
        const int c = idx & 3;
        if (idx < 1024) {
            const int r = (idx & 511) >> 2;
            const __half* src = (idx < 512) ? Ah : Al;
            const uint32_t dst = sbase + ((idx < 512) ? 0 : AREG_B);
            cp16(dst + r * (PITCH * 2) + c * 16,
                 src + (size_t)(mBase + r) * 1024 + k0 + c * 8);
        } else {
            const int q = idx - 1024;
            const int r = q >> 2;
            cp16(sbase + 2 * AREG_B + r * (PITCH * 2) + c * 16,
                 B + (size_t)(nBase + r) * 1024 + k0 + c * 8);
        }
    }
}

__device__ __forceinline__ void mainloop256(
    uint32_t sb,
    const __half* __restrict__ Ah, const __half* __restrict__ Al,
    const __half* __restrict__ B,
    int mBase, int nBase, int tid, int wid, int lid, float acc[2][8][4])
{
    const int wm = (wid >> 2) * 32;
    const int wn = (wid & 3) * 64;
    const int aRow = lid & 15, aCol = (lid >> 4) * 8;
    const int bRow = ((lid >> 4) & 1) * 8 + (lid & 7);
    const int bCol = ((lid >> 3) & 1) * 8;

    load_stage(sb, Ah, Al, B, mBase, nBase, 0, tid);
    asm volatile("cp.async.commit_group;" ::: "memory");
    load_stage(sb + STAGE_B, Ah, Al, B, mBase, nBase, 32, tid);
    asm volatile("cp.async.commit_group;" ::: "memory");

    for (int i = 0; i < 32; ++i) {
        if (i + 1 < 32) asm volatile("cp.async.wait_group 1;" ::: "memory");
        else            asm volatile("cp.async.wait_group 0;" ::: "memory");
        __syncthreads();
        if (i + 2 < 32) {
            load_stage(sb + ((i + 2) % 3) * STAGE_B, Ah, Al, B,
                       mBase, nBase, (i + 2) * 32, tid);
            asm volatile("cp.async.commit_group;" ::: "memory");
        }

        const uint32_t st = sb + (i % 3) * STAGE_B;
        const uint32_t sAh = st, sAl = st + AREG_B;
        const uint32_t sB  = st + 2 * AREG_B;

#pragma unroll
        for (int kk = 0; kk < 32; kk += 16) {
            uint32_t ah[2][4], al[2][4];
#pragma unroll
            for (int mt = 0; mt < 2; mt++) {
                const uint32_t ao = (wm + mt * 16 + aRow) * (PITCH * 2) + (kk + aCol) * 2;
                ldsm_x4(ah[mt][0], ah[mt][1], ah[mt][2], ah[mt][3], sAh + ao);
                ldsm_x4(al[mt][0], al[mt][1], al[mt][2], al[mt][3], sAl + ao);
            }
#pragma unroll
            for (int ntp = 0; ntp < 4; ntp++) {
                const uint32_t bo = (wn + ntp * 16 + bRow) * (PITCH * 2) + (kk + bCol) * 2;
                uint32_t b4[4];
                ldsm_x4(b4[0], b4[1], b4[2], b4[3], sB + bo);
#pragma unroll
                for (int mt = 0; mt < 2; mt++) {
                    mma_f16(acc[mt][2 * ntp],     ah[mt], &b4[0]);
                    mma_f16(acc[mt][2 * ntp],     al[mt], &b4[0]);
                    mma_f16(acc[mt][2 * ntp + 1], ah[mt], &b4[2]);
                    mma_f16(acc[mt][2 * ntp + 1], al[mt], &b4[2]);
                }
            }
        }
    }
}

// ============================================================================
// fused projections: x -> QKV (grid 12x32), y -> KyVy (grid 8x32)
// Q stored hi/lo (A operand of S); K, V stored single fp16 (B operands)
// ============================================================================
__global__ void __launch_bounds__(512, 1)
proj_tc(const __half* __restrict__ Ah, const __half* __restrict__ Al,
        const __half* __restrict__ W, const float* __restrict__ biasC,
        __half* __restrict__ Qh, __half* __restrict__ Ql,
        __half* __restrict__ K, __half* __restrict__ Vt, int is_y)
{
    extern __shared__ __align__(128) char smem[];
    const uint32_t sb = (uint32_t)__cvta_generic_to_shared(smem);
    const int tid = threadIdx.x, wid = tid >> 5, lid = tid & 31;
    const int mBase = blockIdx.y * 128;
    const int nBase = blockIdx.x * 256;

    float acc[2][8][4];
#pragma unroll
    for (int mt = 0; mt < 2; mt++)
#pragma unroll
        for (int nt = 0; nt < 8; nt++)
#pragma unroll
            for (int e = 0; e < 4; e++) acc[mt][nt][e] = 0.f;

    mainloop256(sb, Ah, Al, W, mBase, nBase, tid, wid, lid, acc);

    const int wm = (wid >> 2) * 32, wn = (wid & 3) * 64;
    const int lr = lid >> 2, lc = (lid & 3) * 2;
    const int type0 = ((nBase + wn) >> 10) + is_y;      // 0=Q 1=K 2=V
    const float scale = (type0 == 0) ? 0.125f : 1.f;
    const int seq_off = is_y ? SXX : 0;

#pragma unroll
    for (int mt = 0; mt < 2; mt++) {
#pragma unroll
        for (int half = 0; half < 2; half++) {
            const int m  = mBase + wm + mt * 16 + half * 8 + lr;
            const int bb = m >> 10, sdx = m & 1023;
#pragma unroll
            for (int nt = 0; nt < 8; nt++) {
                const int n = nBase + wn + nt * 8 + lc;
                const float v0 = (acc[mt][nt][half * 2 + 0] + biasC[n])     * scale;
                const float v1 = (acc[mt][nt][half * 2 + 1] + biasC[n + 1]) * scale;
                const int ncol = n & 1023;
                const int hh = ncol >> 6, d = ncol & 63;
                if (type0 == 0) {          // Q: hi/lo, [b,h,s,d]
                    const __half h0 = __float2half_rn(v0);
                    const __half l0 = __float2half_rn(v0 - __half2float(h0));
                    const __half h1 = __float2half_rn(v1);
                    const __half l1 = __float2half_rn(v1 - __half2float(h1));
                    size_t idx = (((size_t)(bb * NH + hh)) * SXX + sdx) * DH + d;
                    *(__half2*)&Qh[idx] = __halves2half2(h0, h1);
                    *(__half2*)&Ql[idx] = __halves2half2(l0, l1);
                } else if (type0 == 1) {   // K: single, [b,h,s,d]
                    size_t idx = (((size_t)(bb * NH + hh)) * SKK + seq_off + sdx) * DH + d;
                    *(__half2*)&K[idx] = __halves2half2(__float2half_rn(v0),
                                                        __float2half_rn(v1));
                } else {                   // V: single, transposed [b,h,d,s]
                    size_t idx = (((size_t)(bb * NH + hh)) * DH + d) * (size_t)SKK
                               + seq_off + sdx;
                    Vt[idx] = __float2half_rn(v0);
                    Vt[idx + SKK] = __float2half_rn(v1);
                }
            }
        }
    }
}

// out projection (grid 4x32): fp32 flat [m, 1024]
__global__ void __launch_bounds__(512, 1)
gemm_out(const __half* __restrict__ Ah, const __half* __restrict__ Al,
         const __half* __restrict__ W, const float* __restrict__ bias,
         float* __restrict__ outF)
{
    extern __shared__ __align__(128) char smem[];
    const uint32_t sb = (uint32_t)__cvta_generic_to_shared(smem);
    const int tid = threadIdx.x, wid = tid >> 5, lid = tid & 31;
    const int mBase = blockIdx.y * 128;
    const int nBase = blockIdx.x * 256;

    float acc[2][8][4];
#pragma unroll
    for (int mt = 0; mt < 2; mt++)
#pragma unroll
        for (int nt = 0; nt < 8; nt++)
#pragma unroll
            for (int e = 0; e < 4; e++) acc[mt][nt][e] = 0.f;

    mainloop256(sb, Ah, Al, W, mBase, nBase, tid, wid, lid, acc);

    const int wm = (wid >> 2) * 32, wn = (wid & 3) * 64;
    const int lr = lid >> 2, lc = (lid & 3) * 2;
#pragma unroll
    for (int mt = 0; mt < 2; mt++)
#pragma unroll
        for (int half = 0; half < 2; half++) {
            const int m = mBase + wm + mt * 16 + half * 8 + lr;
#pragma unroll
            for (int nt = 0; nt < 8; nt++) {
                const int n = nBase + wn + nt * 8 + lc;
                *(float2*)&outF[(size_t)m * DIMN + n] = make_float2(
                    acc[mt][nt][half * 2 + 0] + bias[n],
                    acc[mt][nt][half * 2 + 1] + bias[n + 1]);
            }
        }
}

// ============================================================================
// fp16 tensor-core flash attention: Q hi/lo (A), K/V single (B), 2 MMAs/k16
// smem: KV ring 3 x (K 9216 + V 9216) + Q hi/lo 36864 = 92160
// ============================================================================
#define APITCH   72
#define ATILE_B  (64 * APITCH * 2)           // 9216
#define ASTG     (2 * ATILE_B)               // 18432: K, V
#define AQ_OFF   (3 * ASTG)                  // 55296
#define ATTN_SMEM (AQ_OFF + 2 * 18432)       // 92160

__device__ __forceinline__ void load_kv(
    uint32_t dst, const __half* __restrict__ Kg, const __half* __restrict__ Vg,
    int kt, int tid)
{
#pragma unroll
    for (int j = 0; j < 4; ++j) {
        const int idx = j * 256 + tid;    // 0..1023
        const int t = idx >> 9;           // 0=K, 1=V
        const int q = idx & 511;
        const int r = q >> 3, c = q & 7;
        const uint32_t da = dst + t * ATILE_B + r * (APITCH * 2) + c * 16;
        if (t == 0) cp16(da, Kg + (size_t)(kt * 64 + r) * 64 + c * 8);
        else        cp16(da, Vg + (size_t)r * SKK + kt * 64 + c * 8);
    }
}

__global__ void __launch_bounds__(256, 1)
attn_tc(const __half* __restrict__ Qh, const __half* __restrict__ Ql,
        const __half* __restrict__ K, const __half* __restrict__ Vt,
        __half* __restrict__ Oh, __half* __restrict__ Ol)
{
    extern __shared__ __align__(128) char smem[];
    const uint32_t sb = (uint32_t)__cvta_generic_to_shared(smem);
    const int tid = threadIdx.x, wid = tid >> 5, lid = tid & 31;
    const int qt = blockIdx.x, h = blockIdx.y, b = blockIdx.z;

    const __half* Qgh = Qh + ((size_t)(b * NH + h) * SXX + qt * 128) * DH;
    const __half* Qgl = Ql + ((size_t)(b * NH + h) * SXX + qt * 128) * DH;
    const __half* Kg  = K  + (size_t)(b * NH + h) * SKK * DH;
    const __half* Vg  = Vt + (size_t)(b * NH + h) * DH * SKK;

    load_kv(sb, Kg, Vg, 0, tid);
    asm volatile("cp.async.commit_group;" ::: "memory");
    load_kv(sb + ASTG, Kg, Vg, 1, tid);
    asm volatile("cp.async.commit_group;" ::: "memory");
    // Q hi/lo into persistent region
#pragma unroll
    for (int j = 0; j < 4; ++j) {
        const int q = j * 256 + tid;      // 0..1023
        const int r = q >> 3, c = q & 7;
        cp16(sb + AQ_OFF + r * (APITCH * 2) + c * 16, Qgh + (size_t)r * 64 + c * 8);
        cp16(sb + AQ_OFF + 18432 + r * (APITCH * 2) + c * 16,
             Qgl + (size_t)r * 64 + c * 8);
    }
    asm volatile("cp.async.commit_group;" ::: "memory");
    asm volatile("cp.async.wait_group 0;" ::: "memory");
    __syncthreads();

    uint32_t qhf[4][4], qlf[4][4];
    const int aRow = lid & 15, aCol = (lid >> 4) * 8;
#pragma unroll
    for (int kd = 0; kd < 4; kd++) {
        const uint32_t ao = (wid * 16 + aRow) * (APITCH * 2) + (kd * 16 + aCol) * 2;
        ldsm_x4(qhf[kd][0], qhf[kd][1], qhf[kd][2], qhf[kd][3], sb + AQ_OFF + ao);
        ldsm_x4(qlf[kd][0], qlf[kd][1], qlf[kd][2], qlf[kd][3],
                sb + AQ_OFF + 18432 + ao);
    }

    float m0 = -1e30f, m1 = -1e30f, l0 = 0.f, l1 = 0.f;
    float oacc[8][4];
#pragma unroll
    for (int dt = 0; dt < 8; dt++)
#pragma unroll
        for (int e = 0; e < 4; e++) oacc[dt][e] = 0.f;

    const int bRow = ((lid >> 4) & 1) * 8 + (lid & 7);
    const int bCol = ((lid >> 3) & 1) * 8;

#pragma unroll 1
    for (int kt = 0; kt < 32; ++kt) {
        if (kt + 1 < 32) asm volatile("cp.async.wait_group 1;" ::: "memory");
        else             asm volatile("cp.async.wait_group 0;" ::: "memory");
        __syncthreads();
        if (kt + 2 < 32) {
            load_kv(sb + ((kt + 2) % 3) * ASTG, Kg, Vg, kt + 2, tid);
            asm volatile("cp.async.commit_group;" ::: "memory");
        }
        const uint32_t st = sb + (kt % 3) * ASTG;

        // ---- S = Q @ K^T (2 MMAs per 16x16 subtile) ----
        float sc[8][4];
#pragma unroll
        for (int nt = 0; nt < 8; nt++)
#pragma unroll
            for (int e = 0; e < 4; e++) sc[nt][e] = 0.f;
#pragma unroll
        for (int kd = 0; kd < 4; kd++) {
#pragma unroll
            for (int ntp = 0; ntp < 4; ntp++) {
                const uint32_t bo = (ntp * 16 + bRow) * (APITCH * 2) + (kd * 16 + bCol) * 2;
                uint32_t k4[4];
                ldsm_x4(k4[0], k4[1], k4[2], k4[3], st + bo);
                mma_f16(sc[2 * ntp],     qhf[kd], &k4[0]);
                mma_f16(sc[2 * ntp],     qlf[kd], &k4[0]);
                mma_f16(sc[2 * ntp + 1], qhf[kd], &k4[2]);
                mma_f16(sc[2 * ntp + 1], qlf[kd], &k4[2]);
            }
        }

        // ---- online softmax ----
        float mx0 = -1e30f, mx1 = -1e30f;
#pragma unroll
        for (int nt = 0; nt < 8; nt++) {
            mx0 = fmaxf(mx0, fmaxf(sc[nt][0], sc[nt][1]));
            mx1 = fmaxf(mx1, fmaxf(sc[nt][2], sc[nt][3]));
        }
        mx0 = fmaxf(mx0, __shfl_xor_sync(0xffffffffu, mx0, 1));
        mx0 = fmaxf(mx0, __shfl_xor_sync(0xffffffffu, mx0, 2));
        mx1 = fmaxf(mx1, __shfl_xor_sync(0xffffffffu, mx1, 1));
        mx1 = fmaxf(mx1, __shfl_xor_sync(0xffffffffu, mx1, 2));
        const float mn0 = fmaxf(m0, mx0), mn1 = fmaxf(m1, mx1);
        const float al0 = __expf(m0 - mn0), al1 = __expf(m1 - mn1);
        m0 = mn0; m1 = mn1;
        float rs0 = 0.f, rs1 = 0.f;
#pragma unroll
        for (int nt = 0; nt < 8; nt++) {
            sc[nt][0] = __expf(sc[nt][0] - m0);
            sc[nt][1] = __expf(sc[nt][1] - m0);
            sc[nt][2] = __expf(sc[nt][2] - m1);
            sc[nt][3] = __expf(sc[nt][3] - m1);
            rs0 += sc[nt][0] + sc[nt][1];
            rs1 += sc[nt][2] + sc[nt][3];
        }
        rs0 += __shfl_xor_sync(0xffffffffu, rs0, 1);
        rs0 += __shfl_xor_sync(0xffffffffu, rs0, 2);
        rs1 += __shfl_xor_sync(0xffffffffu, rs1, 1);
        rs1 += __shfl_xor_sync(0xffffffffu, rs1, 2);
        l0 = l0 * al0 + rs0;
        l1 = l1 * al1 + rs1;
#pragma unroll
        for (int dt = 0; dt < 8; dt++) {
            oacc[dt][0] *= al0; oacc[dt][1] *= al0;
            oacc[dt][2] *= al1; oacc[dt][3] *= al1;
        }

        // ---- O += P @ V (P hi/lo fp16, V single) ----
#pragma unroll
        for (int ks = 0; ks < 4; ks++) {
            float p0 = sc[2 * ks][0],     p1 = sc[2 * ks][1];
            float p2 = sc[2 * ks][2],     p3 = sc[2 * ks][3];
            float p4 = sc[2 * ks + 1][0], p5 = sc[2 * ks + 1][1];
            float p6 = sc[2 * ks + 1][2], p7 = sc[2 * ks + 1][3];
            uint32_t pha[4], pla[4];
            pha[0] = pack_f16(p0, p1); pha[1] = pack_f16(p2, p3);
            pha[2] = pack_f16(p4, p5); pha[3] = pack_f16(p6, p7);
            pla[0] = pack_f16(p0 - __half2float(__float2half_rn(p0)),
                              p1 - __half2float(__float2half_rn(p1)));
            pla[1] = pack_f16(p2 - __half2float(__float2half_rn(p2)),
                              p3 - __half2float(__float2half_rn(p3)));
            pla[2] = pack_f16(p4 - __half2float(__float2half_rn(p4)),
                              p5 - __half2float(__float2half_rn(p5)));
            pla[3] = pack_f16(p6 - __half2float(__float2half_rn(p6)),
                              p7 - __half2float(__float2half_rn(p7)));
#pragma unroll
            for (int dtp = 0; dtp < 4; dtp++) {
                const uint32_t vo = (dtp * 16 + bRow) * (APITCH * 2) + (ks * 16 + bCol) * 2;
                uint32_t v4[4];
                ldsm_x4(v4[0], v4[1], v4[2], v4[3], st + ATILE_B + vo);
                mma_f16(oacc[2 * dtp],     pha, &v4[0]);
                mma_f16(oacc[2 * dtp],     pla, &v4[0]);
                mma_f16(oacc[2 * dtp + 1], pha, &v4[2]);
                mma_f16(oacc[2 * dtp + 1], pla, &v4[2]);
            }
        }
    }

    // ---- epilogue: O/l -> fp16 hi/lo, token-major [b,s,dim] ----
    const float inv0 = 1.f / l0, inv1 = 1.f / l1;
    const int row0 = qt * 128 + wid * 16 + (lid >> 2);
    const int row1 = row0 + 8;
    const int lc = (lid & 3) * 2;
#pragma unroll
    for (int dt = 0; dt < 8; dt++) {
        const int col = h * 64 + dt * 8 + lc;
        {
            const float v0 = oacc[dt][0] * inv0, v1 = oacc[dt][1] * inv0;
            const __half h0 = __float2half_rn(v0);
            const __half e0 = __float2half_rn(v0 - __half2float(h0));
            const __half h1 = __float2half_rn(v1);
            const __half e1 = __float2half_rn(v1 - __half2float(h1));
            const size_t i0 = ((size_t)b * SXX + row0) * DIMN + col;
            *(__half2*)&Oh[i0] = __halves2half2(h0, h1);
            *(__half2*)&Ol[i0] = __halves2half2(e0, e1);
        }
        {
            const float v0 = oacc[dt][2] * inv1, v1 = oacc[dt][3] * inv1;
            const __half h0 = __float2half_rn(v0);
            const __half e0 = __float2half_rn(v0 - __half2float(h0));
            const __half h1 = __float2half_rn(v1);
            const __half e1 = __float2half_rn(v1 - __half2float(h1));
            const size_t i1 = ((size_t)b * SXX + row1) * DIMN + col;
            *(__half2*)&Oh[i1] = __halves2half2(h0, h1);
            *(__half2*)&Ol[i1] = __halves2half2(e0, e1);
        }
    }
}

// ============================================================================
// launch
// ============================================================================
extern "C" void kernel_launch(void* const* d_in, const int* in_sizes, int n_in,
                              void* d_out, int out_size)
{
    const float* x     = (const float*)d_in[0];
    const float* y     = (const float*)d_in[1];
    const float* W_Kx  = (const float*)d_in[2];
    const float* b_Kx  = (const float*)d_in[3];
    const float* W_Qx  = (const float*)d_in[4];
    const float* b_Qx  = (const float*)d_in[5];
    const float* W_Vx  = (const float*)d_in[6];
    const float* b_Vx  = (const float*)d_in[7];
    const float* W_Ky  = (const float*)d_in[8];
    const float* b_Ky  = (const float*)d_in[9];
    const float* W_Vy  = (const float*)d_in[10];
    const float* b_Vy  = (const float*)d_in[11];
    const float* W_out = (const float*)d_in[12];
    const float* b_out = (const float*)d_in[13];
    float* out = (float*)d_out;

    __half *xh, *xl, *yh, *yl, *W, *Qhp, *Qlp, *Kp, *Vtp, *Ohp, *Olp;
    float* biasC;
    cudaGetSymbolAddress((void**)&xh, g_xh);   cudaGetSymbolAddress((void**)&xl, g_xl);
    cudaGetSymbolAddress((void**)&yh, g_yh);   cudaGetSymbolAddress((void**)&yl, g_yl);
    cudaGetSymbolAddress((void**)&W, g_W);
    cudaGetSymbolAddress((void**)&biasC, g_bias);
    cudaGetSymbolAddress((void**)&Qhp, g_Qh);  cudaGetSymbolAddress((void**)&Qlp, g_Ql);
    cudaGetSymbolAddress((void**)&Kp, g_K);    cudaGetSymbolAddress((void**)&Vtp, g_Vt);
    cudaGetSymbolAddress((void**)&Ohp, g_Oh);  cudaGetSymbolAddress((void**)&Olp, g_Ol);

    splitxy_kernel<<<8192, 256>>>(x, y, xh, xl, yh, yl);
    cvtW6<<<6168, 256>>>(W_Qx, W_Kx, W_Vx, W_Ky, W_Vy, W_out,
                         b_Qx, b_Kx, b_Vx, b_Ky, b_Vy, b_out, W, biasC);

    cudaFuncSetAttribute(proj_tc,  cudaFuncAttributeMaxDynamicSharedMemorySize, GEMM_SMEM);
    cudaFuncSetAttribute(gemm_out, cudaFuncAttributeMaxDynamicSharedMemorySize, GEMM_SMEM);
    cudaFuncSetAttribute(attn_tc,  cudaFuncAttributeMaxDynamicSharedMemorySize, ATTN_SMEM);

    proj_tc<<<dim3(12, 32), 512, GEMM_SMEM>>>(xh, xl, W, biasC,
                                              Qhp, Qlp, Kp, Vtp, 0);
    proj_tc<<<dim3(8, 32), 512, GEMM_SMEM>>>(yh, yl, W + 3 * 1048576ull,
                                             biasC + 3 * 1024,
                                             Qhp, Qlp, Kp, Vtp, 1);

    attn_tc<<<dim3(8, 16, 4), 256, ATTN_SMEM>>>(Qhp, Qlp, Kp, Vtp, Ohp, Olp);

    gemm_out<<<dim3(4, 32), 512, GEMM_SMEM>>>(Ohp, Olp, W + 5 * 1048576ull,
                                              b_out, out);
}

// round 11
// speedup vs baseline: 2.8022x; 1.1047x over previous
#include <cuda_runtime.h>
#include <cuda_fp16.h>
#include <cstdint>

#define DIMN 1024
#define NH   16
#define DH   64
#define NB   4
#define SXX  1024
#define SKK  2048   // Sx + Sy

// ---- scratch ----
__device__ __half g_xh[4194304], g_xl[4194304];
__device__ __half g_yh[4194304], g_yl[4194304];
__device__ __half g_W[6 * 1048576];            // slots: Qx,Kx,Vx,Ky,Vy,out
__device__ float  g_bias[6144];
__device__ __half g_Qh[4194304], g_Ql[4194304];  // [b,h,s,d] hi/lo
__device__ __half g_K[8388608];                  // [b,h,s,d]  single
__device__ __half g_Vt[8388608];                 // [b,h,d,s]  single
__device__ __half g_O[4194304];                  // [b,s,dim]  single

// ============================================================================
// helpers (sm_80-era PTX only — ptxas target is plain sm_103)
// ============================================================================
__device__ __forceinline__ void cp16(uint32_t s, const void* g) {
    asm volatile("cp.async.cg.shared.global [%0], [%1], 16;"
                 :: "r"(s), "l"(__cvta_generic_to_global(g)) : "memory");
}
__device__ __forceinline__ void ldsm_x4(uint32_t& r0, uint32_t& r1,
                                        uint32_t& r2, uint32_t& r3, uint32_t a) {
    asm volatile("ldmatrix.sync.aligned.m8n8.x4.shared.b16 {%0,%1,%2,%3}, [%4];"
                 : "=r"(r0), "=r"(r1), "=r"(r2), "=r"(r3) : "r"(a));
}
__device__ __forceinline__ void mma_f16(float* c, const uint32_t* a, const uint32_t* b) {
    asm volatile(
        "mma.sync.aligned.m16n8k16.row.col.f32.f16.f16.f32 "
        "{%0,%1,%2,%3}, {%4,%5,%6,%7}, {%8,%9}, {%0,%1,%2,%3};"
        : "+f"(c[0]), "+f"(c[1]), "+f"(c[2]), "+f"(c[3])
        : "r"(a[0]), "r"(a[1]), "r"(a[2]), "r"(a[3]), "r"(b[0]), "r"(b[1]));
}
__device__ __forceinline__ uint32_t pack_f16(float v0, float v1) {
    uint32_t r;
    asm("cvt.rn.f16x2.f32 %0, %1, %2;" : "=r"(r) : "f"(v1), "f"(v0));
    return r;
}

// ============================================================================
// converts
// ============================================================================
__device__ __forceinline__ void split4h(float4 v, __half* hi, __half* lo, size_t i2) {
    __half h0 = __float2half_rn(v.x), h1 = __float2half_rn(v.y);
    __half h2 = __float2half_rn(v.z), h3 = __float2half_rn(v.w);
    __half l0 = __float2half_rn(v.x - __half2float(h0));
    __half l1 = __float2half_rn(v.y - __half2float(h1));
    __half l2 = __float2half_rn(v.z - __half2float(h2));
    __half l3 = __float2half_rn(v.w - __half2float(h3));
    ((__half2*)hi)[i2]     = __halves2half2(h0, h1);
    ((__half2*)hi)[i2 + 1] = __halves2half2(h2, h3);
    ((__half2*)lo)[i2]     = __halves2half2(l0, l1);
    ((__half2*)lo)[i2 + 1] = __halves2half2(l2, l3);
}

__global__ void __launch_bounds__(256)
splitxy_kernel(const float* __restrict__ x, const float* __restrict__ y,
               __half* __restrict__ xh, __half* __restrict__ xl,
               __half* __restrict__ yh, __half* __restrict__ yl)
{
    int i = blockIdx.x * 256 + threadIdx.x;
    if (i < 1048576) split4h(((const float4*)x)[i], xh, xl, 2 * (size_t)i);
    else {
        int j = i - 1048576;
        split4h(((const float4*)y)[j], yh, yl, 2 * (size_t)j);
    }
}

__global__ void __launch_bounds__(256)
cvtW6(const float* s0, const float* s1, const float* s2,
      const float* s3, const float* s4, const float* s5,
      const float* b0, const float* b1, const float* b2,
      const float* b3, const float* b4, const float* b5,
      __half* __restrict__ W, float* __restrict__ biasC)
{
    if (blockIdx.x >= 6144) {
        int i = (blockIdx.x - 6144) * 256 + threadIdx.x;
        int slot = i >> 10, j = i & 1023;
        const float* src = (slot == 0) ? b0 : (slot == 1) ? b1 : (slot == 2) ? b2
                         : (slot == 3) ? b3 : (slot == 4) ? b4 : b5;
        biasC[i] = src[j];
        return;
    }
    int i = blockIdx.x * 256 + threadIdx.x;
    int slot = i >> 18, j = i & 262143;
    const float* src = (slot == 0) ? s0 : (slot == 1) ? s1 : (slot == 2) ? s2
                     : (slot == 3) ? s3 : (slot == 4) ? s4 : s5;
    float4 v = ((const float4*)src)[j];
    ((__half2*)W)[2 * (size_t)i]     = __halves2half2(__float2half_rn(v.x), __float2half_rn(v.y));
    ((__half2*)W)[2 * (size_t)i + 1] = __halves2half2(__float2half_rn(v.z), __float2half_rn(v.w));
}

// ============================================================================
// projections mainloop: A fp16 hi/lo, B single, 2 MMAs/k16 (unchanged)
// ============================================================================
#define PITCH    40
#define AREG_B   (128 * PITCH * 2)           // 10240
#define BREG_B   (256 * PITCH * 2)           // 20480
#define STAGE_B  (2 * AREG_B + BREG_B)       // 40960
#define GEMM_SMEM (3 * STAGE_B)              // 122880

__device__ __forceinline__ void load_stage(
    uint32_t sbase,
    const __half* __restrict__ Ah, const __half* __restrict__ Al,
    const __half* __restrict__ B,
    int mBase, int nBase, int k0, int tid)
{
#pragma unroll
    for (int j = 0; j < 4; ++j) {
        const int idx = j * 512 + tid;
        const int c = idx & 3;
        if (idx < 1024) {
            const int r = (idx & 511) >> 2;
            const __half* src = (idx < 512) ? Ah : Al;
            const uint32_t dst = sbase + ((idx < 512) ? 0 : AREG_B);
            cp16(dst + r * (PITCH * 2) + c * 16,
                 src + (size_t)(mBase + r) * 1024 + k0 + c * 8);
        } else {
            const int q = idx - 1024;
            const int r = q >> 2;
            cp16(sbase + 2 * AREG_B + r * (PITCH * 2) + c * 16,
                 B + (size_t)(nBase + r) * 1024 + k0 + c * 8);
        }
    }
}

__device__ __forceinline__ void mainloop256(
    uint32_t sb,
    const __half* __restrict__ Ah, const __half* __restrict__ Al,
    const __half* __restrict__ B,
    int mBase, int nBase, int tid, int wid, int lid, float acc[2][8][4])
{
    const int wm = (wid >> 2) * 32;
    const int wn = (wid & 3) * 64;
    const int aRow = lid & 15, aCol = (lid >> 4) * 8;
    const int bRow = ((lid >> 4) & 1) * 8 + (lid & 7);
    const int bCol = ((lid >> 3) & 1) * 8;

    load_stage(sb, Ah, Al, B, mBase, nBase, 0, tid);
    asm volatile("cp.async.commit_group;" ::: "memory");
    load_stage(sb + STAGE_B, Ah, Al, B, mBase, nBase, 32, tid);
    asm volatile("cp.async.commit_group;" ::: "memory");

    for (int i = 0; i < 32; ++i) {
        if (i + 1 < 32) asm volatile("cp.async.wait_group 1;" ::: "memory");
        else            asm volatile("cp.async.wait_group 0;" ::: "memory");
        __syncthreads();
        if (i + 2 < 32) {
            load_stage(sb + ((i + 2) % 3) * STAGE_B, Ah, Al, B,
                       mBase, nBase, (i + 2) * 32, tid);
            asm volatile("cp.async.commit_group;" ::: "memory");
        }

        const uint32_t st = sb + (i % 3) * STAGE_B;
        const uint32_t sAh = st, sAl = st + AREG_B;
        const uint32_t sB  = st + 2 * AREG_B;

#pragma unroll
        for (int kk = 0; kk < 32; kk += 16) {
            uint32_t ah[2][4], al[2][4];
#pragma unroll
            for (int mt = 0; mt < 2; mt++) {
                const uint32_t ao = (wm + mt * 16 + aRow) * (PITCH * 2) + (kk + aCol) * 2;
                ldsm_x4(ah[mt][0], ah[mt][1], ah[mt][2], ah[mt][3], sAh + ao);
                ldsm_x4(al[mt][0], al[mt][1], al[mt][2], al[mt][3], sAl + ao);
            }
#pragma unroll
            for (int ntp = 0; ntp < 4; ntp++) {
                const uint32_t bo = (wn + ntp * 16 + bRow) * (PITCH * 2) + (kk + bCol) * 2;
                uint32_t b4[4];
                ldsm_x4(b4[0], b4[1], b4[2], b4[3], sB + bo);
#pragma unroll
                for (int mt = 0; mt < 2; mt++) {
                    mma_f16(acc[mt][2 * ntp],     ah[mt], &b4[0]);
                    mma_f16(acc[mt][2 * ntp],     al[mt], &b4[0]);
                    mma_f16(acc[mt][2 * ntp + 1], ah[mt], &b4[2]);
                    mma_f16(acc[mt][2 * ntp + 1], al[mt], &b4[2]);
                }
            }
        }
    }
}

__global__ void __launch_bounds__(512, 1)
proj_tc(const __half* __restrict__ Ah, const __half* __restrict__ Al,
        const __half* __restrict__ W, const float* __restrict__ biasC,
        __half* __restrict__ Qh, __half* __restrict__ Ql,
        __half* __restrict__ K, __half* __restrict__ Vt, int is_y)
{
    extern __shared__ __align__(128) char smem[];
    const uint32_t sb = (uint32_t)__cvta_generic_to_shared(smem);
    const int tid = threadIdx.x, wid = tid >> 5, lid = tid & 31;
    const int mBase = blockIdx.y * 128;
    const int nBase = blockIdx.x * 256;

    float acc[2][8][4];
#pragma unroll
    for (int mt = 0; mt < 2; mt++)
#pragma unroll
        for (int nt = 0; nt < 8; nt++)
#pragma unroll
            for (int e = 0; e < 4; e++) acc[mt][nt][e] = 0.f;

    mainloop256(sb, Ah, Al, W, mBase, nBase, tid, wid, lid, acc);

    const int wm = (wid >> 2) * 32, wn = (wid & 3) * 64;
    const int lr = lid >> 2, lc = (lid & 3) * 2;
    const int type0 = ((nBase + wn) >> 10) + is_y;      // 0=Q 1=K 2=V
    const float scale = (type0 == 0) ? 0.125f : 1.f;
    const int seq_off = is_y ? SXX : 0;

#pragma unroll
    for (int mt = 0; mt < 2; mt++) {
#pragma unroll
        for (int half = 0; half < 2; half++) {
            const int m  = mBase + wm + mt * 16 + half * 8 + lr;
            const int bb = m >> 10, sdx = m & 1023;
#pragma unroll
            for (int nt = 0; nt < 8; nt++) {
                const int n = nBase + wn + nt * 8 + lc;
                const float v0 = (acc[mt][nt][half * 2 + 0] + biasC[n])     * scale;
                const float v1 = (acc[mt][nt][half * 2 + 1] + biasC[n + 1]) * scale;
                const int ncol = n & 1023;
                const int hh = ncol >> 6, d = ncol & 63;
                if (type0 == 0) {
                    const __half h0 = __float2half_rn(v0);
                    const __half l0 = __float2half_rn(v0 - __half2float(h0));
                    const __half h1 = __float2half_rn(v1);
                    const __half l1 = __float2half_rn(v1 - __half2float(h1));
                    size_t idx = (((size_t)(bb * NH + hh)) * SXX + sdx) * DH + d;
                    *(__half2*)&Qh[idx] = __halves2half2(h0, h1);
                    *(__half2*)&Ql[idx] = __halves2half2(l0, l1);
                } else if (type0 == 1) {
                    size_t idx = (((size_t)(bb * NH + hh)) * SKK + seq_off + sdx) * DH + d;
                    *(__half2*)&K[idx] = __halves2half2(__float2half_rn(v0),
                                                        __float2half_rn(v1));
                } else {
                    size_t idx = (((size_t)(bb * NH + hh)) * DH + d) * (size_t)SKK
                               + seq_off + sdx;
                    Vt[idx] = __float2half_rn(v0);
                    Vt[idx + SKK] = __float2half_rn(v1);
                }
            }
        }
    }
}

// ============================================================================
// out projection: SINGLE x SINGLE fp16, 1 MMA/k16 per subtile (grid 4x32)
// stage: A(128x80B) + B(256x80B) = 30720; 3 stages = 92160
// ============================================================================
#define OSTAGE_B (AREG_B + BREG_B)           // 30720
#define OUT_SMEM (3 * OSTAGE_B)              // 92160

__device__ __forceinline__ void load_stage_out(
    uint32_t sbase, const __half* __restrict__ A, const __half* __restrict__ B,
    int mBase, int nBase, int k0, int tid)
{
#pragma unroll
    for (int j = 0; j < 3; ++j) {
        const int idx = j * 512 + tid;    // 0..1535
        const int c = idx & 3;
        if (idx < 512) {
            const int r = idx >> 2;
            cp16(sbase + r * (PITCH * 2) + c * 16,
                 A + (size_t)(mBase + r) * 1024 + k0 + c * 8);
        } else {
            const int q = idx - 512;
            const int r = q >> 2;
            cp16(sbase + AREG_B + r * (PITCH * 2) + c * 16,
                 B + (size_t)(nBase + r) * 1024 + k0 + c * 8);
        }
    }
}

__global__ void __launch_bounds__(512, 1)
gemm_out(const __half* __restrict__ A, const __half* __restrict__ W,
         const float* __restrict__ bias, float* __restrict__ outF)
{
    extern __shared__ __align__(128) char smem[];
    const uint32_t sb = (uint32_t)__cvta_generic_to_shared(smem);
    const int tid = threadIdx.x, wid = tid >> 5, lid = tid & 31;
    const int mBase = blockIdx.y * 128;
    const int nBase = blockIdx.x * 256;
    const int wm = (wid >> 2) * 32;
    const int wn = (wid & 3) * 64;
    const int aRow = lid & 15, aCol = (lid >> 4) * 8;
    const int bRow = ((lid >> 4) & 1) * 8 + (lid & 7);
    const int bCol = ((lid >> 3) & 1) * 8;

    float acc[2][8][4];
#pragma unroll
    for (int mt = 0; mt < 2; mt++)
#pragma unroll
        for (int nt = 0; nt < 8; nt++)
#pragma unroll
            for (int e = 0; e < 4; e++) acc[mt][nt][e] = 0.f;

    load_stage_out(sb, A, W, mBase, nBase, 0, tid);
    asm volatile("cp.async.commit_group;" ::: "memory");
    load_stage_out(sb + OSTAGE_B, A, W, mBase, nBase, 32, tid);
    asm volatile("cp.async.commit_group;" ::: "memory");

    for (int i = 0; i < 32; ++i) {
        if (i + 1 < 32) asm volatile("cp.async.wait_group 1;" ::: "memory");
        else            asm volatile("cp.async.wait_group 0;" ::: "memory");
        __syncthreads();
        if (i + 2 < 32) {
            load_stage_out(sb + ((i + 2) % 3) * OSTAGE_B, A, W,
                           mBase, nBase, (i + 2) * 32, tid);
            asm volatile("cp.async.commit_group;" ::: "memory");
        }

        const uint32_t st = sb + (i % 3) * OSTAGE_B;
        const uint32_t sA = st, sB = st + AREG_B;

#pragma unroll
        for (int kk = 0; kk < 32; kk += 16) {
            uint32_t a4[2][4];
#pragma unroll
            for (int mt = 0; mt < 2; mt++) {
                const uint32_t ao = (wm + mt * 16 + aRow) * (PITCH * 2) + (kk + aCol) * 2;
                ldsm_x4(a4[mt][0], a4[mt][1], a4[mt][2], a4[mt][3], sA + ao);
            }
#pragma unroll
            for (int ntp = 0; ntp < 4; ntp++) {
                const uint32_t bo = (wn + ntp * 16 + bRow) * (PITCH * 2) + (kk + bCol) * 2;
                uint32_t b4[4];
                ldsm_x4(b4[0], b4[1], b4[2], b4[3], sB + bo);
#pragma unroll
                for (int mt = 0; mt < 2; mt++) {
                    mma_f16(acc[mt][2 * ntp],     a4[mt], &b4[0]);
                    mma_f16(acc[mt][2 * ntp + 1], a4[mt], &b4[2]);
                }
            }
        }
    }

    const int lr = lid >> 2, lc = (lid & 3) * 2;
#pragma unroll
    for (int mt = 0; mt < 2; mt++)
#pragma unroll
        for (int half = 0; half < 2; half++) {
            const int m = mBase + wm + mt * 16 + half * 8 + lr;
#pragma unroll
            for (int nt = 0; nt < 8; nt++) {
                const int n = nBase + wn + nt * 8 + lc;
                *(float2*)&outF[(size_t)m * DIMN + n] = make_float2(
                    acc[mt][nt][half * 2 + 0] + bias[n],
                    acc[mt][nt][half * 2 + 1] + bias[n + 1]);
            }
        }
}

// ============================================================================
// fp16 flash attention: Q hi/lo for S; P single for PV; O single fp16 out
// ============================================================================
#define APITCH   72
#define ATILE_B  (64 * APITCH * 2)           // 9216
#define ASTG     (2 * ATILE_B)               // 18432: K, V
#define AQ_OFF   (3 * ASTG)                  // 55296
#define ATTN_SMEM (AQ_OFF + 2 * 18432)       // 92160

__device__ __forceinline__ void load_kv(
    uint32_t dst, const __half* __restrict__ Kg, const __half* __restrict__ Vg,
    int kt, int tid)
{
#pragma unroll
    for (int j = 0; j < 4; ++j) {
        const int idx = j * 256 + tid;
        const int t = idx >> 9;
        const int q = idx & 511;
        const int r = q >> 3, c = q & 7;
        const uint32_t da = dst + t * ATILE_B + r * (APITCH * 2) + c * 16;
        if (t == 0) cp16(da, Kg + (size_t)(kt * 64 + r) * 64 + c * 8);
        else        cp16(da, Vg + (size_t)r * SKK + kt * 64 + c * 8);
    }
}

__global__ void __launch_bounds__(256, 1)
attn_tc(const __half* __restrict__ Qh, const __half* __restrict__ Ql,
        const __half* __restrict__ K, const __half* __restrict__ Vt,
        __half* __restrict__ O)
{
    extern __shared__ __align__(128) char smem[];
    const uint32_t sb = (uint32_t)__cvta_generic_to_shared(smem);
    const int tid = threadIdx.x, wid = tid >> 5, lid = tid & 31;
    const int qt = blockIdx.x, h = blockIdx.y, b = blockIdx.z;

    const __half* Qgh = Qh + ((size_t)(b * NH + h) * SXX + qt * 128) * DH;
    const __half* Qgl = Ql + ((size_t)(b * NH + h) * SXX + qt * 128) * DH;
    const __half* Kg  = K  + (size_t)(b * NH + h) * SKK * DH;
    const __half* Vg  = Vt + (size_t)(b * NH + h) * DH * SKK;

    load_kv(sb, Kg, Vg, 0, tid);
    asm volatile("cp.async.commit_group;" ::: "memory");
    load_kv(sb + ASTG, Kg, Vg, 1, tid);
    asm volatile("cp.async.commit_group;" ::: "memory");
#pragma unroll
    for (int j = 0; j < 4; ++j) {
        const int q = j * 256 + tid;
        const int r = q >> 3, c = q & 7;
        cp16(sb + AQ_OFF + r * (APITCH * 2) + c * 16, Qgh + (size_t)r * 64 + c * 8);
        cp16(sb + AQ_OFF + 18432 + r * (APITCH * 2) + c * 16,
             Qgl + (size_t)r * 64 + c * 8);
    }
    asm volatile("cp.async.commit_group;" ::: "memory");
    asm volatile("cp.async.wait_group 0;" ::: "memory");
    __syncthreads();

    uint32_t qhf[4][4], qlf[4][4];
    const int aRow = lid & 15, aCol = (lid >> 4) * 8;
#pragma unroll
    for (int kd = 0; kd < 4; kd++) {
        const uint32_t ao = (wid * 16 + aRow) * (APITCH * 2) + (kd * 16 + aCol) * 2;
        ldsm_x4(qhf[kd][0], qhf[kd][1], qhf[kd][2], qhf[kd][3], sb + AQ_OFF + ao);
        ldsm_x4(qlf[kd][0], qlf[kd][1], qlf[kd][2], qlf[kd][3],
                sb + AQ_OFF + 18432 + ao);
    }

    float m0 = -1e30f, m1 = -1e30f, l0 = 0.f, l1 = 0.f;
    float oacc[8][4];
#pragma unroll
    for (int dt = 0; dt < 8; dt++)
#pragma unroll
        for (int e = 0; e < 4; e++) oacc[dt][e] = 0.f;

    const int bRow = ((lid >> 4) & 1) * 8 + (lid & 7);
    const int bCol = ((lid >> 3) & 1) * 8;

#pragma unroll 1
    for (int kt = 0; kt < 32; ++kt) {
        if (kt + 1 < 32) asm volatile("cp.async.wait_group 1;" ::: "memory");
        else             asm volatile("cp.async.wait_group 0;" ::: "memory");
        __syncthreads();
        if (kt + 2 < 32) {
            load_kv(sb + ((kt + 2) % 3) * ASTG, Kg, Vg, kt + 2, tid);
            asm volatile("cp.async.commit_group;" ::: "memory");
        }
        const uint32_t st = sb + (kt % 3) * ASTG;

        // ---- S = Q @ K^T (hi/lo Q) ----
        float sc[8][4];
#pragma unroll
        for (int nt = 0; nt < 8; nt++)
#pragma unroll
            for (int e = 0; e < 4; e++) sc[nt][e] = 0.f;
#pragma unroll
        for (int kd = 0; kd < 4; kd++) {
#pragma unroll
            for (int ntp = 0; ntp < 4; ntp++) {
                const uint32_t bo = (ntp * 16 + bRow) * (APITCH * 2) + (kd * 16 + bCol) * 2;
                uint32_t k4[4];
                ldsm_x4(k4[0], k4[1], k4[2], k4[3], st + bo);
                mma_f16(sc[2 * ntp],     qhf[kd], &k4[0]);
                mma_f16(sc[2 * ntp],     qlf[kd], &k4[0]);
                mma_f16(sc[2 * ntp + 1], qhf[kd], &k4[2]);
                mma_f16(sc[2 * ntp + 1], qlf[kd], &k4[2]);
            }
        }

        // ---- online softmax ----
        float mx0 = -1e30f, mx1 = -1e30f;
#pragma unroll
        for (int nt = 0; nt < 8; nt++) {
            mx0 = fmaxf(mx0, fmaxf(sc[nt][0], sc[nt][1]));
            mx1 = fmaxf(mx1, fmaxf(sc[nt][2], sc[nt][3]));
        }
        mx0 = fmaxf(mx0, __shfl_xor_sync(0xffffffffu, mx0, 1));
        mx0 = fmaxf(mx0, __shfl_xor_sync(0xffffffffu, mx0, 2));
        mx1 = fmaxf(mx1, __shfl_xor_sync(0xffffffffu, mx1, 1));
        mx1 = fmaxf(mx1, __shfl_xor_sync(0xffffffffu, mx1, 2));
        const float mn0 = fmaxf(m0, mx0), mn1 = fmaxf(m1, mx1);
        const float al0 = __expf(m0 - mn0), al1 = __expf(m1 - mn1);
        m0 = mn0; m1 = mn1;
        float rs0 = 0.f, rs1 = 0.f;
#pragma unroll
        for (int nt = 0; nt < 8; nt++) {
            sc[nt][0] = __expf(sc[nt][0] - m0);
            sc[nt][1] = __expf(sc[nt][1] - m0);
            sc[nt][2] = __expf(sc[nt][2] - m1);
            sc[nt][3] = __expf(sc[nt][3] - m1);
            rs0 += sc[nt][0] + sc[nt][1];
            rs1 += sc[nt][2] + sc[nt][3];
        }
        rs0 += __shfl_xor_sync(0xffffffffu, rs0, 1);
        rs0 += __shfl_xor_sync(0xffffffffu, rs0, 2);
        rs1 += __shfl_xor_sync(0xffffffffu, rs1, 1);
        rs1 += __shfl_xor_sync(0xffffffffu, rs1, 2);
        l0 = l0 * al0 + rs0;
        l1 = l1 * al1 + rs1;
#pragma unroll
        for (int dt = 0; dt < 8; dt++) {
            oacc[dt][0] *= al0; oacc[dt][1] *= al0;
            oacc[dt][2] *= al1; oacc[dt][3] *= al1;
        }

        // ---- O += P @ V (P single fp16 — lo term dropped) ----
#pragma unroll
        for (int ks = 0; ks < 4; ks++) {
            uint32_t pha[4];
            pha[0] = pack_f16(sc[2 * ks][0],     sc[2 * ks][1]);
            pha[1] = pack_f16(sc[2 * ks][2],     sc[2 * ks][3]);
            pha[2] = pack_f16(sc[2 * ks + 1][0], sc[2 * ks + 1][1]);
            pha[3] = pack_f16(sc[2 * ks + 1][2], sc[2 * ks + 1][3]);
#pragma unroll
            for (int dtp = 0; dtp < 4; dtp++) {
                const uint32_t vo = (dtp * 16 + bRow) * (APITCH * 2) + (ks * 16 + bCol) * 2;
                uint32_t v4[4];
                ldsm_x4(v4[0], v4[1], v4[2], v4[3], st + ATILE_B + vo);
                mma_f16(oacc[2 * dtp],     pha, &v4[0]);
                mma_f16(oacc[2 * dtp + 1], pha, &v4[2]);
            }
        }
    }

    // ---- epilogue: O/l -> single fp16, token-major [b,s,dim] ----
    const float inv0 = 1.f / l0, inv1 = 1.f / l1;
    const int row0 = qt * 128 + wid * 16 + (lid >> 2);
    const int row1 = row0 + 8;
    const int lc = (lid & 3) * 2;
#pragma unroll
    for (int dt = 0; dt < 8; dt++) {
        const int col = h * 64 + dt * 8 + lc;
        {
            const size_t i0 = ((size_t)b * SXX + row0) * DIMN + col;
            *(__half2*)&O[i0] = __halves2half2(__float2half_rn(oacc[dt][0] * inv0),
                                               __float2half_rn(oacc[dt][1] * inv0));
        }
        {
            const size_t i1 = ((size_t)b * SXX + row1) * DIMN + col;
            *(__half2*)&O[i1] = __halves2half2(__float2half_rn(oacc[dt][2] * inv1),
                                               __float2half_rn(oacc[dt][3] * inv1));
        }
    }
}

// ============================================================================
// launch
// ============================================================================
extern "C" void kernel_launch(void* const* d_in, const int* in_sizes, int n_in,
                              void* d_out, int out_size)
{
    const float* x     = (const float*)d_in[0];
    const float* y     = (const float*)d_in[1];
    const float* W_Kx  = (const float*)d_in[2];
    const float* b_Kx  = (const float*)d_in[3];
    const float* W_Qx  = (const float*)d_in[4];
    const float* b_Qx  = (const float*)d_in[5];
    const float* W_Vx  = (const float*)d_in[6];
    const float* b_Vx  = (const float*)d_in[7];
    const float* W_Ky  = (const float*)d_in[8];
    const float* b_Ky  = (const float*)d_in[9];
    const float* W_Vy  = (const float*)d_in[10];
    const float* b_Vy  = (const float*)d_in[11];
    const float* W_out = (const float*)d_in[12];
    const float* b_out = (const float*)d_in[13];
    float* out = (float*)d_out;

    __half *xh, *xl, *yh, *yl, *W, *Qhp, *Qlp, *Kp, *Vtp, *Op;
    float* biasC;
    cudaGetSymbolAddress((void**)&xh, g_xh);   cudaGetSymbolAddress((void**)&xl, g_xl);
    cudaGetSymbolAddress((void**)&yh, g_yh);   cudaGetSymbolAddress((void**)&yl, g_yl);
    cudaGetSymbolAddress((void**)&W, g_W);
    cudaGetSymbolAddress((void**)&biasC, g_bias);
    cudaGetSymbolAddress((void**)&Qhp, g_Qh);  cudaGetSymbolAddress((void**)&Qlp, g_Ql);
    cudaGetSymbolAddress((void**)&Kp, g_K);    cudaGetSymbolAddress((void**)&Vtp, g_Vt);
    cudaGetSymbolAddress((void**)&Op, g_O);

    splitxy_kernel<<<8192, 256>>>(x, y, xh, xl, yh, yl);
    cvtW6<<<6168, 256>>>(W_Qx, W_Kx, W_Vx, W_Ky, W_Vy, W_out,
                         b_Qx, b_Kx, b_Vx, b_Ky, b_Vy, b_out, W, biasC);

    cudaFuncSetAttribute(proj_tc,  cudaFuncAttributeMaxDynamicSharedMemorySize, GEMM_SMEM);
    cudaFuncSetAttribute(gemm_out, cudaFuncAttributeMaxDynamicSharedMemorySize, OUT_SMEM);
    cudaFuncSetAttribute(attn_tc,  cudaFuncAttributeMaxDynamicSharedMemorySize, ATTN_SMEM);

    proj_tc<<<dim3(12, 32), 512, GEMM_SMEM>>>(xh, xl, W, biasC,
                                              Qhp, Qlp, Kp, Vtp, 0);
    proj_tc<<<dim3(8, 32), 512, GEMM_SMEM>>>(yh, yl, W + 3 * 1048576ull,
                                             biasC + 3 * 1024,
                                             Qhp, Qlp, Kp, Vtp, 1);

    attn_tc<<<dim3(8, 16, 4), 256, ATTN_SMEM>>>(Qhp, Qlp, Kp, Vtp, Op);

    gemm_out<<<dim3(4, 32), 512, OUT_SMEM>>>(Op, W + 5 * 1048576ull, b_out, out);
}

// round 12
// speedup vs baseline: 3.6354x; 1.2974x over previous
#include <cuda_runtime.h>
#include <cuda_fp16.h>
#include <cstdint>

#define DIMN 1024
#define NH   16
#define DH   64
#define NB   4
#define SXX  1024
#define SKK  2048   // Sx + Sy

// ---- scratch (all single fp16) ----
__device__ __half g_x[4194304], g_y[4194304];
__device__ __half g_W[6 * 1048576];            // slots: Qx,Kx,Vx,Ky,Vy,out
__device__ float  g_bias[6144];
__device__ __half g_Q[4194304];                  // [b,h,s,d]
__device__ __half g_K[8388608];                  // [b,h,s,d]
__device__ __half g_Vt[8388608];                 // [b,h,d,s]
__device__ __half g_O[4194304];                  // [b,s,dim]

// ============================================================================
// helpers (sm_80-era PTX only — ptxas target is plain sm_103)
// ============================================================================
__device__ __forceinline__ void cp16(uint32_t s, const void* g) {
    asm volatile("cp.async.cg.shared.global [%0], [%1], 16;"
                 :: "r"(s), "l"(__cvta_generic_to_global(g)) : "memory");
}
__device__ __forceinline__ void ldsm_x4(uint32_t& r0, uint32_t& r1,
                                        uint32_t& r2, uint32_t& r3, uint32_t a) {
    asm volatile("ldmatrix.sync.aligned.m8n8.x4.shared.b16 {%0,%1,%2,%3}, [%4];"
                 : "=r"(r0), "=r"(r1), "=r"(r2), "=r"(r3) : "r"(a));
}
__device__ __forceinline__ void mma_f16(float* c, const uint32_t* a, const uint32_t* b) {
    asm volatile(
        "mma.sync.aligned.m16n8k16.row.col.f32.f16.f16.f32 "
        "{%0,%1,%2,%3}, {%4,%5,%6,%7}, {%8,%9}, {%0,%1,%2,%3};"
        : "+f"(c[0]), "+f"(c[1]), "+f"(c[2]), "+f"(c[3])
        : "r"(a[0]), "r"(a[1]), "r"(a[2]), "r"(a[3]), "r"(b[0]), "r"(b[1]));
}
__device__ __forceinline__ uint32_t pack_f16(float v0, float v1) {
    uint32_t r;
    asm("cvt.rn.f16x2.f32 %0, %1, %2;" : "=r"(r) : "f"(v1), "f"(v0));
    return r;
}

// ============================================================================
// converts: fp32 -> single fp16
// ============================================================================
__global__ void __launch_bounds__(256)
cvtxy_kernel(const float* __restrict__ x, const float* __restrict__ y,
             __half* __restrict__ xo, __half* __restrict__ yo)
{
    int i = blockIdx.x * 256 + threadIdx.x;
    const float* src; __half* dst; int j;
    if (i < 1048576) { src = x; dst = xo; j = i; }
    else             { src = y; dst = yo; j = i - 1048576; }
    float4 v = ((const float4*)src)[j];
    ((__half2*)dst)[2 * (size_t)j]     = __halves2half2(__float2half_rn(v.x), __float2half_rn(v.y));
    ((__half2*)dst)[2 * (size_t)j + 1] = __halves2half2(__float2half_rn(v.z), __float2half_rn(v.w));
}

__global__ void __launch_bounds__(256)
cvtW6(const float* s0, const float* s1, const float* s2,
      const float* s3, const float* s4, const float* s5,
      const float* b0, const float* b1, const float* b2,
      const float* b3, const float* b4, const float* b5,
      __half* __restrict__ W, float* __restrict__ biasC)
{
    if (blockIdx.x >= 6144) {
        int i = (blockIdx.x - 6144) * 256 + threadIdx.x;
        int slot = i >> 10, j = i & 1023;
        const float* src = (slot == 0) ? b0 : (slot == 1) ? b1 : (slot == 2) ? b2
                         : (slot == 3) ? b3 : (slot == 4) ? b4 : b5;
        biasC[i] = src[j];
        return;
    }
    int i = blockIdx.x * 256 + threadIdx.x;
    int slot = i >> 18, j = i & 262143;
    const float* src = (slot == 0) ? s0 : (slot == 1) ? s1 : (slot == 2) ? s2
                     : (slot == 3) ? s3 : (slot == 4) ? s4 : s5;
    float4 v = ((const float4*)src)[j];
    ((__half2*)W)[2 * (size_t)i]     = __halves2half2(__float2half_rn(v.x), __float2half_rn(v.y));
    ((__half2*)W)[2 * (size_t)i + 1] = __halves2half2(__float2half_rn(v.z), __float2half_rn(v.w));
}

// ============================================================================
// single x single 128(M) x 256(N) x K=1024 mainloop, 1 MMA/k16 per subtile
// 512 threads / 16 warps (4m x 4n), warp tile 32x64, 3-stage cp.async
// ============================================================================
#define PITCH    40
#define AREG_B   (128 * PITCH * 2)           // 10240
#define BREG_B   (256 * PITCH * 2)           // 20480
#define OSTAGE_B (AREG_B + BREG_B)           // 30720
#define GEMM_SMEM (3 * OSTAGE_B)             // 92160

__device__ __forceinline__ void load_stage_s(
    uint32_t sbase, const __half* __restrict__ A, const __half* __restrict__ B,
    int mBase, int nBase, int k0, int tid)
{
#pragma unroll
    for (int j = 0; j < 3; ++j) {
        const int idx = j * 512 + tid;    // 0..1535
        const int c = idx & 3;
        if (idx < 512) {
            const int r = idx >> 2;
            cp16(sbase + r * (PITCH * 2) + c * 16,
                 A + (size_t)(mBase + r) * 1024 + k0 + c * 8);
        } else {
            const int q = idx - 512;
            const int r = q >> 2;
            cp16(sbase + AREG_B + r * (PITCH * 2) + c * 16,
                 B + (size_t)(nBase + r) * 1024 + k0 + c * 8);
        }
    }
}

__device__ __forceinline__ void mainloop256s(
    uint32_t sb, const __half* __restrict__ A, const __half* __restrict__ B,
    int mBase, int nBase, int tid, int wid, int lid, float acc[2][8][4])
{
    const int wm = (wid >> 2) * 32;
    const int wn = (wid & 3) * 64;
    const int aRow = lid & 15, aCol = (lid >> 4) * 8;
    const int bRow = ((lid >> 4) & 1) * 8 + (lid & 7);
    const int bCol = ((lid >> 3) & 1) * 8;

    load_stage_s(sb, A, B, mBase, nBase, 0, tid);
    asm volatile("cp.async.commit_group;" ::: "memory");
    load_stage_s(sb + OSTAGE_B, A, B, mBase, nBase, 32, tid);
    asm volatile("cp.async.commit_group;" ::: "memory");

    for (int i = 0; i < 32; ++i) {
        if (i + 1 < 32) asm volatile("cp.async.wait_group 1;" ::: "memory");
        else            asm volatile("cp.async.wait_group 0;" ::: "memory");
        __syncthreads();
        if (i + 2 < 32) {
            load_stage_s(sb + ((i + 2) % 3) * OSTAGE_B, A, B,
                         mBase, nBase, (i + 2) * 32, tid);
            asm volatile("cp.async.commit_group;" ::: "memory");
        }

        const uint32_t st = sb + (i % 3) * OSTAGE_B;
        const uint32_t sA = st, sB = st + AREG_B;

#pragma unroll
        for (int kk = 0; kk < 32; kk += 16) {
            uint32_t a4[2][4];
#pragma unroll
            for (int mt = 0; mt < 2; mt++) {
                const uint32_t ao = (wm + mt * 16 + aRow) * (PITCH * 2) + (kk + aCol) * 2;
                ldsm_x4(a4[mt][0], a4[mt][1], a4[mt][2], a4[mt][3], sA + ao);
            }
#pragma unroll
            for (int ntp = 0; ntp < 4; ntp++) {
                const uint32_t bo = (wn + ntp * 16 + bRow) * (PITCH * 2) + (kk + bCol) * 2;
                uint32_t b4[4];
                ldsm_x4(b4[0], b4[1], b4[2], b4[3], sB + bo);
#pragma unroll
                for (int mt = 0; mt < 2; mt++) {
                    mma_f16(acc[mt][2 * ntp],     a4[mt], &b4[0]);
                    mma_f16(acc[mt][2 * ntp + 1], a4[mt], &b4[2]);
                }
            }
        }
    }
}

// ============================================================================
// fused projections: x -> QKV (grid 12x32), y -> KyVy (grid 8x32)
// ============================================================================
__global__ void __launch_bounds__(512, 1)
proj_tc(const __half* __restrict__ A, const __half* __restrict__ W,
        const float* __restrict__ biasC,
        __half* __restrict__ Q, __half* __restrict__ K,
        __half* __restrict__ Vt, int is_y)
{
    extern __shared__ __align__(128) char smem[];
    const uint32_t sb = (uint32_t)__cvta_generic_to_shared(smem);
    const int tid = threadIdx.x, wid = tid >> 5, lid = tid & 31;
    const int mBase = blockIdx.y * 128;
    const int nBase = blockIdx.x * 256;

    float acc[2][8][4];
#pragma unroll
    for (int mt = 0; mt < 2; mt++)
#pragma unroll
        for (int nt = 0; nt < 8; nt++)
#pragma unroll
            for (int e = 0; e < 4; e++) acc[mt][nt][e] = 0.f;

    mainloop256s(sb, A, W, mBase, nBase, tid, wid, lid, acc);

    const int wm = (wid >> 2) * 32, wn = (wid & 3) * 64;
    const int lr = lid >> 2, lc = (lid & 3) * 2;
    const int type0 = ((nBase + wn) >> 10) + is_y;      // 0=Q 1=K 2=V
    const float scale = (type0 == 0) ? 0.125f : 1.f;
    const int seq_off = is_y ? SXX : 0;

#pragma unroll
    for (int mt = 0; mt < 2; mt++) {
#pragma unroll
        for (int half = 0; half < 2; half++) {
            const int m  = mBase + wm + mt * 16 + half * 8 + lr;
            const int bb = m >> 10, sdx = m & 1023;
#pragma unroll
            for (int nt = 0; nt < 8; nt++) {
                const int n = nBase + wn + nt * 8 + lc;
                const float v0 = (acc[mt][nt][half * 2 + 0] + biasC[n])     * scale;
                const float v1 = (acc[mt][nt][half * 2 + 1] + biasC[n + 1]) * scale;
                const int ncol = n & 1023;
                const int hh = ncol >> 6, d = ncol & 63;
                if (type0 == 0) {
                    size_t idx = (((size_t)(bb * NH + hh)) * SXX + sdx) * DH + d;
                    *(__half2*)&Q[idx] = __halves2half2(__float2half_rn(v0),
                                                        __float2half_rn(v1));
                } else if (type0 == 1) {
                    size_t idx = (((size_t)(bb * NH + hh)) * SKK + seq_off + sdx) * DH + d;
                    *(__half2*)&K[idx] = __halves2half2(__float2half_rn(v0),
                                                        __float2half_rn(v1));
                } else {
                    size_t idx = (((size_t)(bb * NH + hh)) * DH + d) * (size_t)SKK
                               + seq_off + sdx;
                    Vt[idx] = __float2half_rn(v0);
                    Vt[idx + SKK] = __float2half_rn(v1);
                }
            }
        }
    }
}

// out projection (grid 4x32): fp32 flat [m, 1024]
__global__ void __launch_bounds__(512, 1)
gemm_out(const __half* __restrict__ A, const __half* __restrict__ W,
         const float* __restrict__ bias, float* __restrict__ outF)
{
    extern __shared__ __align__(128) char smem[];
    const uint32_t sb = (uint32_t)__cvta_generic_to_shared(smem);
    const int tid = threadIdx.x, wid = tid >> 5, lid = tid & 31;
    const int mBase = blockIdx.y * 128;
    const int nBase = blockIdx.x * 256;

    float acc[2][8][4];
#pragma unroll
    for (int mt = 0; mt < 2; mt++)
#pragma unroll
        for (int nt = 0; nt < 8; nt++)
#pragma unroll
            for (int e = 0; e < 4; e++) acc[mt][nt][e] = 0.f;

    mainloop256s(sb, A, W, mBase, nBase, tid, wid, lid, acc);

    const int wm = (wid >> 2) * 32, wn = (wid & 3) * 64;
    const int lr = lid >> 2, lc = (lid & 3) * 2;
#pragma unroll
    for (int mt = 0; mt < 2; mt++)
#pragma unroll
        for (int half = 0; half < 2; half++) {
            const int m = mBase + wm + mt * 16 + half * 8 + lr;
#pragma unroll
            for (int nt = 0; nt < 8; nt++) {
                const int n = nBase + wn + nt * 8 + lc;
                *(float2*)&outF[(size_t)m * DIMN + n] = make_float2(
                    acc[mt][nt][half * 2 + 0] + bias[n],
                    acc[mt][nt][half * 2 + 1] + bias[n + 1]);
            }
        }
}

// ============================================================================
// fp16 flash attention, all-single: 1 MMA per S subtile, 1 per PV subtile
// smem: KV ring 3 x 18432 + Q 18432 = 73728
// ============================================================================
#define APITCH   72
#define ATILE_B  (64 * APITCH * 2)           // 9216
#define ASTG     (2 * ATILE_B)               // 18432: K, V
#define AQ_OFF   (3 * ASTG)                  // 55296
#define ATTN_SMEM (AQ_OFF + 18432)           // 73728

__device__ __forceinline__ void load_kv(
    uint32_t dst, const __half* __restrict__ Kg, const __half* __restrict__ Vg,
    int kt, int tid)
{
#pragma unroll
    for (int j = 0; j < 4; ++j) {
        const int idx = j * 256 + tid;
        const int t = idx >> 9;
        const int q = idx & 511;
        const int r = q >> 3, c = q & 7;
        const uint32_t da = dst + t * ATILE_B + r * (APITCH * 2) + c * 16;
        if (t == 0) cp16(da, Kg + (size_t)(kt * 64 + r) * 64 + c * 8);
        else        cp16(da, Vg + (size_t)r * SKK + kt * 64 + c * 8);
    }
}

__global__ void __launch_bounds__(256, 1)
attn_tc(const __half* __restrict__ Q, const __half* __restrict__ K,
        const __half* __restrict__ Vt, __half* __restrict__ O)
{
    extern __shared__ __align__(128) char smem[];
    const uint32_t sb = (uint32_t)__cvta_generic_to_shared(smem);
    const int tid = threadIdx.x, wid = tid >> 5, lid = tid & 31;
    const int qt = blockIdx.x, h = blockIdx.y, b = blockIdx.z;

    const __half* Qg = Q + ((size_t)(b * NH + h) * SXX + qt * 128) * DH;
    const __half* Kg = K + (size_t)(b * NH + h) * SKK * DH;
    const __half* Vg = Vt + (size_t)(b * NH + h) * DH * SKK;

    load_kv(sb, Kg, Vg, 0, tid);
    asm volatile("cp.async.commit_group;" ::: "memory");
    load_kv(sb + ASTG, Kg, Vg, 1, tid);
    asm volatile("cp.async.commit_group;" ::: "memory");
#pragma unroll
    for (int j = 0; j < 4; ++j) {
        const int q = j * 256 + tid;
        const int r = q >> 3, c = q & 7;
        cp16(sb + AQ_OFF + r * (APITCH * 2) + c * 16, Qg + (size_t)r * 64 + c * 8);
    }
    asm volatile("cp.async.commit_group;" ::: "memory");
    asm volatile("cp.async.wait_group 0;" ::: "memory");
    __syncthreads();

    uint32_t qf[4][4];
    const int aRow = lid & 15, aCol = (lid >> 4) * 8;
#pragma unroll
    for (int kd = 0; kd < 4; kd++) {
        const uint32_t ao = (wid * 16 + aRow) * (APITCH * 2) + (kd * 16 + aCol) * 2;
        ldsm_x4(qf[kd][0], qf[kd][1], qf[kd][2], qf[kd][3], sb + AQ_OFF + ao);
    }

    float m0 = -1e30f, m1 = -1e30f, l0 = 0.f, l1 = 0.f;
    float oacc[8][4];
#pragma unroll
    for (int dt = 0; dt < 8; dt++)
#pragma unroll
        for (int e = 0; e < 4; e++) oacc[dt][e] = 0.f;

    const int bRow = ((lid >> 4) & 1) * 8 + (lid & 7);
    const int bCol = ((lid >> 3) & 1) * 8;

#pragma unroll 1
    for (int kt = 0; kt < 32; ++kt) {
        if (kt + 1 < 32) asm volatile("cp.async.wait_group 1;" ::: "memory");
        else             asm volatile("cp.async.wait_group 0;" ::: "memory");
        __syncthreads();
        if (kt + 2 < 32) {
            load_kv(sb + ((kt + 2) % 3) * ASTG, Kg, Vg, kt + 2, tid);
            asm volatile("cp.async.commit_group;" ::: "memory");
        }
        const uint32_t st = sb + (kt % 3) * ASTG;

        // ---- S = Q @ K^T (single) ----
        float sc[8][4];
#pragma unroll
        for (int nt = 0; nt < 8; nt++)
#pragma unroll
            for (int e = 0; e < 4; e++) sc[nt][e] = 0.f;
#pragma unroll
        for (int kd = 0; kd < 4; kd++) {
#pragma unroll
            for (int ntp = 0; ntp < 4; ntp++) {
                const uint32_t bo = (ntp * 16 + bRow) * (APITCH * 2) + (kd * 16 + bCol) * 2;
                uint32_t k4[4];
                ldsm_x4(k4[0], k4[1], k4[2], k4[3], st + bo);
                mma_f16(sc[2 * ntp],     qf[kd], &k4[0]);
                mma_f16(sc[2 * ntp + 1], qf[kd], &k4[2]);
            }
        }

        // ---- online softmax ----
        float mx0 = -1e30f, mx1 = -1e30f;
#pragma unroll
        for (int nt = 0; nt < 8; nt++) {
            mx0 = fmaxf(mx0, fmaxf(sc[nt][0], sc[nt][1]));
            mx1 = fmaxf(mx1, fmaxf(sc[nt][2], sc[nt][3]));
        }
        mx0 = fmaxf(mx0, __shfl_xor_sync(0xffffffffu, mx0, 1));
        mx0 = fmaxf(mx0, __shfl_xor_sync(0xffffffffu, mx0, 2));
        mx1 = fmaxf(mx1, __shfl_xor_sync(0xffffffffu, mx1, 1));
        mx1 = fmaxf(mx1, __shfl_xor_sync(0xffffffffu, mx1, 2));
        const float mn0 = fmaxf(m0, mx0), mn1 = fmaxf(m1, mx1);
        const float al0 = __expf(m0 - mn0), al1 = __expf(m1 - mn1);
        m0 = mn0; m1 = mn1;
        float rs0 = 0.f, rs1 = 0.f;
#pragma unroll
        for (int nt = 0; nt < 8; nt++) {
            sc[nt][0] = __expf(sc[nt][0] - m0);
            sc[nt][1] = __expf(sc[nt][1] - m0);
            sc[nt][2] = __expf(sc[nt][2] - m1);
            sc[nt][3] = __expf(sc[nt][3] - m1);
            rs0 += sc[nt][0] + sc[nt][1];
            rs1 += sc[nt][2] + sc[nt][3];
        }
        rs0 += __shfl_xor_sync(0xffffffffu, rs0, 1);
        rs0 += __shfl_xor_sync(0xffffffffu, rs0, 2);
        rs1 += __shfl_xor_sync(0xffffffffu, rs1, 1);
        rs1 += __shfl_xor_sync(0xffffffffu, rs1, 2);
        l0 = l0 * al0 + rs0;
        l1 = l1 * al1 + rs1;
#pragma unroll
        for (int dt = 0; dt < 8; dt++) {
            oacc[dt][0] *= al0; oacc[dt][1] *= al0;
            oacc[dt][2] *= al1; oacc[dt][3] *= al1;
        }

        // ---- O += P @ V (single) ----
#pragma unroll
        for (int ks = 0; ks < 4; ks++) {
            uint32_t pha[4];
            pha[0] = pack_f16(sc[2 * ks][0],     sc[2 * ks][1]);
            pha[1] = pack_f16(sc[2 * ks][2],     sc[2 * ks][3]);
            pha[2] = pack_f16(sc[2 * ks + 1][0], sc[2 * ks + 1][1]);
            pha[3] = pack_f16(sc[2 * ks + 1][2], sc[2 * ks + 1][3]);
#pragma unroll
            for (int dtp = 0; dtp < 4; dtp++) {
                const uint32_t vo = (dtp * 16 + bRow) * (APITCH * 2) + (ks * 16 + bCol) * 2;
                uint32_t v4[4];
                ldsm_x4(v4[0], v4[1], v4[2], v4[3], st + ATILE_B + vo);
                mma_f16(oacc[2 * dtp],     pha, &v4[0]);
                mma_f16(oacc[2 * dtp + 1], pha, &v4[2]);
            }
        }
    }

    // ---- epilogue ----
    const float inv0 = 1.f / l0, inv1 = 1.f / l1;
    const int row0 = qt * 128 + wid * 16 + (lid >> 2);
    const int row1 = row0 + 8;
    const int lc = (lid & 3) * 2;
#pragma unroll
    for (int dt = 0; dt < 8; dt++) {
        const int col = h * 64 + dt * 8 + lc;
        {
            const size_t i0 = ((size_t)b * SXX + row0) * DIMN + col;
            *(__half2*)&O[i0] = __halves2half2(__float2half_rn(oacc[dt][0] * inv0),
                                               __float2half_rn(oacc[dt][1] * inv0));
        }
        {
            const size_t i1 = ((size_t)b * SXX + row1) * DIMN + col;
            *(__half2*)&O[i1] = __halves2half2(__float2half_rn(oacc[dt][2] * inv1),
                                               __float2half_rn(oacc[dt][3] * inv1));
        }
    }
}

// ============================================================================
// launch
// ============================================================================
extern "C" void kernel_launch(void* const* d_in, const int* in_sizes, int n_in,
                              void* d_out, int out_size)
{
    const float* x     = (const float*)d_in[0];
    const float* y     = (const float*)d_in[1];
    const float* W_Kx  = (const float*)d_in[2];
    const float* b_Kx  = (const float*)d_in[3];
    const float* W_Qx  = (const float*)d_in[4];
    const float* b_Qx  = (const float*)d_in[5];
    const float* W_Vx  = (const float*)d_in[6];
    const float* b_Vx  = (const float*)d_in[7];
    const float* W_Ky  = (const float*)d_in[8];
    const float* b_Ky  = (const float*)d_in[9];
    const float* W_Vy  = (const float*)d_in[10];
    const float* b_Vy  = (const float*)d_in[11];
    const float* W_out = (const float*)d_in[12];
    const float* b_out = (const float*)d_in[13];
    float* out = (float*)d_out;

    __half *xp, *yp, *W, *Qp, *Kp, *Vtp, *Op;
    float* biasC;
    cudaGetSymbolAddress((void**)&xp, g_x);   cudaGetSymbolAddress((void**)&yp, g_y);
    cudaGetSymbolAddress((void**)&W, g_W);
    cudaGetSymbolAddress((void**)&biasC, g_bias);
    cudaGetSymbolAddress((void**)&Qp, g_Q);   cudaGetSymbolAddress((void**)&Kp, g_K);
    cudaGetSymbolAddress((void**)&Vtp, g_Vt); cudaGetSymbolAddress((void**)&Op, g_O);

    cvtxy_kernel<<<8192, 256>>>(x, y, xp, yp);
    cvtW6<<<6168, 256>>>(W_Qx, W_Kx, W_Vx, W_Ky, W_Vy, W_out,
                         b_Qx, b_Kx, b_Vx, b_Ky, b_Vy, b_out, W, biasC);

    cudaFuncSetAttribute(proj_tc,  cudaFuncAttributeMaxDynamicSharedMemorySize, GEMM_SMEM);
    cudaFuncSetAttribute(gemm_out, cudaFuncAttributeMaxDynamicSharedMemorySize, GEMM_SMEM);
    cudaFuncSetAttribute(attn_tc,  cudaFuncAttributeMaxDynamicSharedMemorySize, ATTN_SMEM);

    proj_tc<<<dim3(12, 32), 512, GEMM_SMEM>>>(xp, W, biasC, Qp, Kp, Vtp, 0);
    proj_tc<<<dim3(8, 32), 512, GEMM_SMEM>>>(yp, W + 3 * 1048576ull,
                                             biasC + 3 * 1024, Qp, Kp, Vtp, 1);

    attn_tc<<<dim3(8, 16, 4), 256, ATTN_SMEM>>>(Qp, Kp, Vtp, Op);

    gemm_out<<<dim3(4, 32), 512, GEMM_SMEM>>>(Op, W + 5 * 1048576ull, b_out, out);
}

// round 13
// speedup vs baseline: 4.3561x; 1.1982x over previous
#include <cuda_runtime.h>
#include <cuda_fp16.h>
#include <cstdint>

#define DIMN 1024
#define NH   16
#define DH   64
#define NB   4
#define SXX  1024
#define SKK  2048   // Sx + Sy

// ---- scratch (all single fp16) ----
__device__ __half g_x[4194304], g_y[4194304];
__device__ __half g_W[6 * 1048576];            // slots: Qx,Kx,Vx,Ky,Vy,out
__device__ float  g_bias[6144];
__device__ __half g_Q[4194304];                  // [b,h,s,d]
__device__ __half g_K[8388608];                  // [b,h,s,d]
__device__ __half g_Vt[8388608];                 // [b,h,d,s]
__device__ __half g_O[4194304];                  // [b,s,dim]

// ============================================================================
// helpers (sm_80-era PTX only — ptxas target is plain sm_103)
// ============================================================================
__device__ __forceinline__ void cp16(uint32_t s, const void* g) {
    asm volatile("cp.async.cg.shared.global [%0], [%1], 16;"
                 :: "r"(s), "l"(__cvta_generic_to_global(g)) : "memory");
}
__device__ __forceinline__ void ldsm_x4(uint32_t& r0, uint32_t& r1,
                                        uint32_t& r2, uint32_t& r3, uint32_t a) {
    asm volatile("ldmatrix.sync.aligned.m8n8.x4.shared.b16 {%0,%1,%2,%3}, [%4];"
                 : "=r"(r0), "=r"(r1), "=r"(r2), "=r"(r3) : "r"(a));
}
__device__ __forceinline__ void mma_f16(float* c, const uint32_t* a, const uint32_t* b) {
    asm volatile(
        "mma.sync.aligned.m16n8k16.row.col.f32.f16.f16.f32 "
        "{%0,%1,%2,%3}, {%4,%5,%6,%7}, {%8,%9}, {%0,%1,%2,%3};"
        : "+f"(c[0]), "+f"(c[1]), "+f"(c[2]), "+f"(c[3])
        : "r"(a[0]), "r"(a[1]), "r"(a[2]), "r"(a[3]), "r"(b[0]), "r"(b[1]));
}
__device__ __forceinline__ uint32_t pack_f16(float v0, float v1) {
    uint32_t r;
    asm("cvt.rn.f16x2.f32 %0, %1, %2;" : "=r"(r) : "f"(v1), "f"(v0));
    return r;
}

// ============================================================================
// converts
// ============================================================================
__global__ void __launch_bounds__(256)
cvtxy_kernel(const float* __restrict__ x, const float* __restrict__ y,
             __half* __restrict__ xo, __half* __restrict__ yo)
{
    int i = blockIdx.x * 256 + threadIdx.x;
    const float* src; __half* dst; int j;
    if (i < 1048576) { src = x; dst = xo; j = i; }
    else             { src = y; dst = yo; j = i - 1048576; }
    float4 v = ((const float4*)src)[j];
    ((__half2*)dst)[2 * (size_t)j]     = __halves2half2(__float2half_rn(v.x), __float2half_rn(v.y));
    ((__half2*)dst)[2 * (size_t)j + 1] = __halves2half2(__float2half_rn(v.z), __float2half_rn(v.w));
}

__global__ void __launch_bounds__(256)
cvtW6(const float* s0, const float* s1, const float* s2,
      const float* s3, const float* s4, const float* s5,
      const float* b0, const float* b1, const float* b2,
      const float* b3, const float* b4, const float* b5,
      __half* __restrict__ W, float* __restrict__ biasC)
{
    if (blockIdx.x >= 6144) {
        int i = (blockIdx.x - 6144) * 256 + threadIdx.x;
        int slot = i >> 10, j = i & 1023;
        const float* src = (slot == 0) ? b0 : (slot == 1) ? b1 : (slot == 2) ? b2
                         : (slot == 3) ? b3 : (slot == 4) ? b4 : b5;
        biasC[i] = src[j];
        return;
    }
    int i = blockIdx.x * 256 + threadIdx.x;
    int slot = i >> 18, j = i & 262143;
    const float* src = (slot == 0) ? s0 : (slot == 1) ? s1 : (slot == 2) ? s2
                     : (slot == 3) ? s3 : (slot == 4) ? s4 : s5;
    float4 v = ((const float4*)src)[j];
    ((__half2*)W)[2 * (size_t)i]     = __halves2half2(__float2half_rn(v.x), __float2half_rn(v.y));
    ((__half2*)W)[2 * (size_t)i + 1] = __halves2half2(__float2half_rn(v.z), __float2half_rn(v.w));
}

// ============================================================================
// GEMM mainloop: 128(M) x 256(N) x 1024, 256 threads / 8 warps (2m x 4n),
// warp tile 64x64, K-chunk 64 per stage (16 iters), 3-stage cp.async.
// smem rows: 144B pitch (64 halves data + pad) — conflict-free ldmatrix.
// ============================================================================
#define GPITCH_B  144
#define GA_B      (128 * GPITCH_B)           // 18432
#define GB_B      (256 * GPITCH_B)           // 36864
#define GSTG_B    (GA_B + GB_B)              // 55296
#define GEMM_SMEM (3 * GSTG_B)               // 165888

__device__ __forceinline__ void load_stage_g(
    uint32_t sbase, const __half* __restrict__ A, const __half* __restrict__ B,
    int mBase, int nBase, int k0, int tid)
{
#pragma unroll
    for (int j = 0; j < 12; ++j) {
        const int idx = j * 256 + tid;    // 0..3071
        if (idx < 1024) {
            const int r = idx >> 3, c = idx & 7;
            cp16(sbase + r * GPITCH_B + c * 16,
                 A + (size_t)(mBase + r) * 1024 + k0 + c * 8);
        } else {
            const int q = idx - 1024;
            const int r = q >> 3, c = q & 7;
            cp16(sbase + GA_B + r * GPITCH_B + c * 16,
                 B + (size_t)(nBase + r) * 1024 + k0 + c * 8);
        }
    }
}

__device__ __forceinline__ void mainloop_g(
    uint32_t sb, const __half* __restrict__ A, const __half* __restrict__ B,
    int mBase, int nBase, int tid, int wid, int lid, float acc[4][8][4])
{
    const int wm = (wid >> 2) * 64;          // 2 m-groups of 64
    const int wn = (wid & 3) * 64;           // 4 n-groups of 64
    const int aRow = lid & 15, aCol = (lid >> 4) * 8;
    const int bRow = ((lid >> 4) & 1) * 8 + (lid & 7);
    const int bCol = ((lid >> 3) & 1) * 8;

    load_stage_g(sb, A, B, mBase, nBase, 0, tid);
    asm volatile("cp.async.commit_group;" ::: "memory");
    load_stage_g(sb + GSTG_B, A, B, mBase, nBase, 64, tid);
    asm volatile("cp.async.commit_group;" ::: "memory");

    for (int i = 0; i < 16; ++i) {
        if (i + 1 < 16) asm volatile("cp.async.wait_group 1;" ::: "memory");
        else            asm volatile("cp.async.wait_group 0;" ::: "memory");
        __syncthreads();
        if (i + 2 < 16) {
            load_stage_g(sb + ((i + 2) % 3) * GSTG_B, A, B,
                         mBase, nBase, (i + 2) * 64, tid);
            asm volatile("cp.async.commit_group;" ::: "memory");
        }

        const uint32_t st = sb + (i % 3) * GSTG_B;
        const uint32_t sA = st, sB = st + GA_B;

#pragma unroll
        for (int kk = 0; kk < 64; kk += 16) {
            uint32_t a4[4][4];
#pragma unroll
            for (int mt = 0; mt < 4; mt++) {
                const uint32_t ao = (wm + mt * 16 + aRow) * GPITCH_B + (kk + aCol) * 2;
                ldsm_x4(a4[mt][0], a4[mt][1], a4[mt][2], a4[mt][3], sA + ao);
            }
#pragma unroll
            for (int ntp = 0; ntp < 4; ntp++) {
                const uint32_t bo = (wn + ntp * 16 + bRow) * GPITCH_B + (kk + bCol) * 2;
                uint32_t b4[4];
                ldsm_x4(b4[0], b4[1], b4[2], b4[3], sB + bo);
#pragma unroll
                for (int mt = 0; mt < 4; mt++) {
                    mma_f16(acc[mt][2 * ntp],     a4[mt], &b4[0]);
                    mma_f16(acc[mt][2 * ntp + 1], a4[mt], &b4[2]);
                }
            }
        }
    }
}

// ============================================================================
// fused projections: x -> QKV (grid 12x32), y -> KyVy (grid 8x32)
// ============================================================================
__global__ void __launch_bounds__(256, 1)
proj_tc(const __half* __restrict__ A, const __half* __restrict__ W,
        const float* __restrict__ biasC,
        __half* __restrict__ Q, __half* __restrict__ K,
        __half* __restrict__ Vt, int is_y)
{
    extern __shared__ __align__(128) char smem[];
    const uint32_t sb = (uint32_t)__cvta_generic_to_shared(smem);
    const int tid = threadIdx.x, wid = tid >> 5, lid = tid & 31;
    const int mBase = blockIdx.y * 128;
    const int nBase = blockIdx.x * 256;

    float acc[4][8][4];
#pragma unroll
    for (int mt = 0; mt < 4; mt++)
#pragma unroll
        for (int nt = 0; nt < 8; nt++)
#pragma unroll
            for (int e = 0; e < 4; e++) acc[mt][nt][e] = 0.f;

    mainloop_g(sb, A, W, mBase, nBase, tid, wid, lid, acc);

    const int wm = (wid >> 2) * 64, wn = (wid & 3) * 64;
    const int lr = lid >> 2, lc = (lid & 3) * 2;
    const int type0 = ((nBase + wn) >> 10) + is_y;      // 0=Q 1=K 2=V
    const float scale = (type0 == 0) ? 0.125f : 1.f;
    const int seq_off = is_y ? SXX : 0;

#pragma unroll
    for (int mt = 0; mt < 4; mt++) {
#pragma unroll
        for (int half = 0; half < 2; half++) {
            const int m  = mBase + wm + mt * 16 + half * 8 + lr;
            const int bb = m >> 10, sdx = m & 1023;
#pragma unroll
            for (int nt = 0; nt < 8; nt++) {
                const int n = nBase + wn + nt * 8 + lc;
                const float v0 = (acc[mt][nt][half * 2 + 0] + biasC[n])     * scale;
                const float v1 = (acc[mt][nt][half * 2 + 1] + biasC[n + 1]) * scale;
                const int ncol = n & 1023;
                const int hh = ncol >> 6, d = ncol & 63;
                if (type0 == 0) {
                    size_t idx = (((size_t)(bb * NH + hh)) * SXX + sdx) * DH + d;
                    *(__half2*)&Q[idx] = __halves2half2(__float2half_rn(v0),
                                                        __float2half_rn(v1));
                } else if (type0 == 1) {
                    size_t idx = (((size_t)(bb * NH + hh)) * SKK + seq_off + sdx) * DH + d;
                    *(__half2*)&K[idx] = __halves2half2(__float2half_rn(v0),
                                                        __float2half_rn(v1));
                } else {
                    size_t idx = (((size_t)(bb * NH + hh)) * DH + d) * (size_t)SKK
                               + seq_off + sdx;
                    Vt[idx] = __float2half_rn(v0);
                    Vt[idx + SKK] = __float2half_rn(v1);
                }
            }
        }
    }
}

// out projection (grid 4x32): fp32 flat [m, 1024]
__global__ void __launch_bounds__(256, 1)
gemm_out(const __half* __restrict__ A, const __half* __restrict__ W,
         const float* __restrict__ bias, float* __restrict__ outF)
{
    extern __shared__ __align__(128) char smem[];
    const uint32_t sb = (uint32_t)__cvta_generic_to_shared(smem);
    const int tid = threadIdx.x, wid = tid >> 5, lid = tid & 31;
    const int mBase = blockIdx.y * 128;
    const int nBase = blockIdx.x * 256;

    float acc[4][8][4];
#pragma unroll
    for (int mt = 0; mt < 4; mt++)
#pragma unroll
        for (int nt = 0; nt < 8; nt++)
#pragma unroll
            for (int e = 0; e < 4; e++) acc[mt][nt][e] = 0.f;

    mainloop_g(sb, A, W, mBase, nBase, tid, wid, lid, acc);

    const int wm = (wid >> 2) * 64, wn = (wid & 3) * 64;
    const int lr = lid >> 2, lc = (lid & 3) * 2;
#pragma unroll
    for (int mt = 0; mt < 4; mt++)
#pragma unroll
        for (int half = 0; half < 2; half++) {
            const int m = mBase + wm + mt * 16 + half * 8 + lr;
#pragma unroll
            for (int nt = 0; nt < 8; nt++) {
                const int n = nBase + wn + nt * 8 + lc;
                *(float2*)&outF[(size_t)m * DIMN + n] = make_float2(
                    acc[mt][nt][half * 2 + 0] + bias[n],
                    acc[mt][nt][half * 2 + 1] + bias[n + 1]);
            }
        }
}

// ============================================================================
// fp16 flash attention: 256 q-rows per CTA, 8 warps x 32 q-rows (2 m-subtiles)
// K/V tiles 64 keys, 3-stage. S-phase: 4 LDSM : 16 MMA per kd-step.
// smem: KV ring 3x18432 + Q 256x144 = 92160
// ============================================================================
#define APITCH_B  144
#define ATILE_B   (64 * APITCH_B)            // 9216
#define ASTG      (2 * ATILE_B)              // 18432
#define AQ_OFF    (3 * ASTG)                 // 55296
#define ATTN_SMEM (AQ_OFF + 256 * APITCH_B)  // 92160

__device__ __forceinline__ void load_kv(
    uint32_t dst, const __half* __restrict__ Kg, const __half* __restrict__ Vg,
    int kt, int tid)
{
#pragma unroll
    for (int j = 0; j < 4; ++j) {
        const int idx = j * 256 + tid;
        const int t = idx >> 9;
        const int q = idx & 511;
        const int r = q >> 3, c = q & 7;
        const uint32_t da = dst + t * ATILE_B + r * APITCH_B + c * 16;
        if (t == 0) cp16(da, Kg + (size_t)(kt * 64 + r) * 64 + c * 8);
        else        cp16(da, Vg + (size_t)r * SKK + kt * 64 + c * 8);
    }
}

__global__ void __launch_bounds__(256, 1)
attn_tc(const __half* __restrict__ Q, const __half* __restrict__ K,
        const __half* __restrict__ Vt, __half* __restrict__ O)
{
    extern __shared__ __align__(128) char smem[];
    const uint32_t sb = (uint32_t)__cvta_generic_to_shared(smem);
    const int tid = threadIdx.x, wid = tid >> 5, lid = tid & 31;
    const int qt = blockIdx.x, h = blockIdx.y, b = blockIdx.z;

    const __half* Qg = Q + ((size_t)(b * NH + h) * SXX + qt * 256) * DH;
    const __half* Kg = K + (size_t)(b * NH + h) * SKK * DH;
    const __half* Vg = Vt + (size_t)(b * NH + h) * DH * SKK;

    load_kv(sb, Kg, Vg, 0, tid);
    asm volatile("cp.async.commit_group;" ::: "memory");
    load_kv(sb + ASTG, Kg, Vg, 1, tid);
    asm volatile("cp.async.commit_group;" ::: "memory");
    // Q: 256 rows x 8 chunks = 2048
#pragma unroll
    for (int j = 0; j < 8; ++j) {
        const int q = j * 256 + tid;
        const int r = q >> 3, c = q & 7;
        cp16(sb + AQ_OFF + r * APITCH_B + c * 16, Qg + (size_t)r * 64 + c * 8);
    }
    asm volatile("cp.async.commit_group;" ::: "memory");
    asm volatile("cp.async.wait_group 0;" ::: "memory");
    __syncthreads();

    // Q frags: 2 m-subtiles x 4 kd
    uint32_t qf[2][4][4];
    const int aRow = lid & 15, aCol = (lid >> 4) * 8;
#pragma unroll
    for (int mt = 0; mt < 2; mt++)
#pragma unroll
        for (int kd = 0; kd < 4; kd++) {
            const uint32_t ao = (wid * 32 + mt * 16 + aRow) * APITCH_B + (kd * 16 + aCol) * 2;
            ldsm_x4(qf[mt][kd][0], qf[mt][kd][1], qf[mt][kd][2], qf[mt][kd][3],
                    sb + AQ_OFF + ao);
        }

    float mi[2][2], li[2][2];
#pragma unroll
    for (int mt = 0; mt < 2; mt++) { mi[mt][0] = mi[mt][1] = -1e30f;
                                     li[mt][0] = li[mt][1] = 0.f; }
    float oacc[2][8][4];
#pragma unroll
    for (int mt = 0; mt < 2; mt++)
#pragma unroll
        for (int dt = 0; dt < 8; dt++)
#pragma unroll
            for (int e = 0; e < 4; e++) oacc[mt][dt][e] = 0.f;

    const int bRow = ((lid >> 4) & 1) * 8 + (lid & 7);
    const int bCol = ((lid >> 3) & 1) * 8;

#pragma unroll 1
    for (int kt = 0; kt < 32; ++kt) {
        if (kt + 1 < 32) asm volatile("cp.async.wait_group 1;" ::: "memory");
        else             asm volatile("cp.async.wait_group 0;" ::: "memory");
        __syncthreads();
        if (kt + 2 < 32) {
            load_kv(sb + ((kt + 2) % 3) * ASTG, Kg, Vg, kt + 2, tid);
            asm volatile("cp.async.commit_group;" ::: "memory");
        }
        const uint32_t st = sb + (kt % 3) * ASTG;

        // ---- S = Q @ K^T ----
        float sc[2][8][4];
#pragma unroll
        for (int mt = 0; mt < 2; mt++)
#pragma unroll
            for (int nt = 0; nt < 8; nt++)
#pragma unroll
                for (int e = 0; e < 4; e++) sc[mt][nt][e] = 0.f;
#pragma unroll
        for (int kd = 0; kd < 4; kd++) {
#pragma unroll
            for (int ntp = 0; ntp < 4; ntp++) {
                const uint32_t bo = (ntp * 16 + bRow) * APITCH_B + (kd * 16 + bCol) * 2;
                uint32_t k4[4];
                ldsm_x4(k4[0], k4[1], k4[2], k4[3], st + bo);
#pragma unroll
                for (int mt = 0; mt < 2; mt++) {
                    mma_f16(sc[mt][2 * ntp],     qf[mt][kd], &k4[0]);
                    mma_f16(sc[mt][2 * ntp + 1], qf[mt][kd], &k4[2]);
                }
            }
        }

        // ---- online softmax per m-subtile ----
#pragma unroll
        for (int mt = 0; mt < 2; mt++) {
            float mx0 = -1e30f, mx1 = -1e30f;
#pragma unroll
            for (int nt = 0; nt < 8; nt++) {
                mx0 = fmaxf(mx0, fmaxf(sc[mt][nt][0], sc[mt][nt][1]));
                mx1 = fmaxf(mx1, fmaxf(sc[mt][nt][2], sc[mt][nt][3]));
            }
            mx0 = fmaxf(mx0, __shfl_xor_sync(0xffffffffu, mx0, 1));
            mx0 = fmaxf(mx0, __shfl_xor_sync(0xffffffffu, mx0, 2));
            mx1 = fmaxf(mx1, __shfl_xor_sync(0xffffffffu, mx1, 1));
            mx1 = fmaxf(mx1, __shfl_xor_sync(0xffffffffu, mx1, 2));
            const float mn0 = fmaxf(mi[mt][0], mx0), mn1 = fmaxf(mi[mt][1], mx1);
            const float al0 = __expf(mi[mt][0] - mn0), al1 = __expf(mi[mt][1] - mn1);
            mi[mt][0] = mn0; mi[mt][1] = mn1;
            float rs0 = 0.f, rs1 = 0.f;
#pragma unroll
            for (int nt = 0; nt < 8; nt++) {
                sc[mt][nt][0] = __expf(sc[mt][nt][0] - mn0);
                sc[mt][nt][1] = __expf(sc[mt][nt][1] - mn0);
                sc[mt][nt][2] = __expf(sc[mt][nt][2] - mn1);
                sc[mt][nt][3] = __expf(sc[mt][nt][3] - mn1);
                rs0 += sc[mt][nt][0] + sc[mt][nt][1];
                rs1 += sc[mt][nt][2] + sc[mt][nt][3];
            }
            rs0 += __shfl_xor_sync(0xffffffffu, rs0, 1);
            rs0 += __shfl_xor_sync(0xffffffffu, rs0, 2);
            rs1 += __shfl_xor_sync(0xffffffffu, rs1, 1);
            rs1 += __shfl_xor_sync(0xffffffffu, rs1, 2);
            li[mt][0] = li[mt][0] * al0 + rs0;
            li[mt][1] = li[mt][1] * al1 + rs1;
#pragma unroll
            for (int dt = 0; dt < 8; dt++) {
                oacc[mt][dt][0] *= al0; oacc[mt][dt][1] *= al0;
                oacc[mt][dt][2] *= al1; oacc[mt][dt][3] *= al1;
            }
        }

        // ---- O += P @ V ----
#pragma unroll
        for (int ks = 0; ks < 4; ks++) {
            uint32_t pha[2][4];
#pragma unroll
            for (int mt = 0; mt < 2; mt++) {
                pha[mt][0] = pack_f16(sc[mt][2 * ks][0],     sc[mt][2 * ks][1]);
                pha[mt][1] = pack_f16(sc[mt][2 * ks][2],     sc[mt][2 * ks][3]);
                pha[mt][2] = pack_f16(sc[mt][2 * ks + 1][0], sc[mt][2 * ks + 1][1]);
                pha[mt][3] = pack_f16(sc[mt][2 * ks + 1][2], sc[mt][2 * ks + 1][3]);
            }
#pragma unroll
            for (int dtp = 0; dtp < 4; dtp++) {
                const uint32_t vo = (dtp * 16 + bRow) * APITCH_B + (ks * 16 + bCol) * 2;
                uint32_t v4[4];
                ldsm_x4(v4[0], v4[1], v4[2], v4[3], st + ATILE_B + vo);
#pragma unroll
                for (int mt = 0; mt < 2; mt++) {
                    mma_f16(oacc[mt][2 * dtp],     pha[mt], &v4[0]);
                    mma_f16(oacc[mt][2 * dtp + 1], pha[mt], &v4[2]);
                }
            }
        }
    }

    // ---- epilogue ----
    const int lc = (lid & 3) * 2;
#pragma unroll
    for (int mt = 0; mt < 2; mt++) {
        const float inv0 = 1.f / li[mt][0], inv1 = 1.f / li[mt][1];
        const int row0 = qt * 256 + wid * 32 + mt * 16 + (lid >> 2);
        const int row1 = row0 + 8;
#pragma unroll
        for (int dt = 0; dt < 8; dt++) {
            const int col = h * 64 + dt * 8 + lc;
            {
                const size_t i0 = ((size_t)b * SXX + row0) * DIMN + col;
                *(__half2*)&O[i0] = __halves2half2(__float2half_rn(oacc[mt][dt][0] * inv0),
                                                   __float2half_rn(oacc[mt][dt][1] * inv0));
            }
            {
                const size_t i1 = ((size_t)b * SXX + row1) * DIMN + col;
                *(__half2*)&O[i1] = __halves2half2(__float2half_rn(oacc[mt][dt][2] * inv1),
                                                   __float2half_rn(oacc[mt][dt][3] * inv1));
            }
        }
    }
}

// ============================================================================
// launch
// ============================================================================
extern "C" void kernel_launch(void* const* d_in, const int* in_sizes, int n_in,
                              void* d_out, int out_size)
{
    const float* x     = (const float*)d_in[0];
    const float* y     = (const float*)d_in[1];
    const float* W_Kx  = (const float*)d_in[2];
    const float* b_Kx  = (const float*)d_in[3];
    const float* W_Qx  = (const float*)d_in[4];
    const float* b_Qx  = (const float*)d_in[5];
    const float* W_Vx  = (const float*)d_in[6];
    const float* b_Vx  = (const float*)d_in[7];
    const float* W_Ky  = (const float*)d_in[8];
    const float* b_Ky  = (const float*)d_in[9];
    const float* W_Vy  = (const float*)d_in[10];
    const float* b_Vy  = (const float*)d_in[11];
    const float* W_out = (const float*)d_in[12];
    const float* b_out = (const float*)d_in[13];
    float* out = (float*)d_out;

    __half *xp, *yp, *W, *Qp, *Kp, *Vtp, *Op;
    float* biasC;
    cudaGetSymbolAddress((void**)&xp, g_x);   cudaGetSymbolAddress((void**)&yp, g_y);
    cudaGetSymbolAddress((void**)&W, g_W);
    cudaGetSymbolAddress((void**)&biasC, g_bias);
    cudaGetSymbolAddress((void**)&Qp, g_Q);   cudaGetSymbolAddress((void**)&Kp, g_K);
    cudaGetSymbolAddress((void**)&Vtp, g_Vt); cudaGetSymbolAddress((void**)&Op, g_O);

    cvtxy_kernel<<<8192, 256>>>(x, y, xp, yp);
    cvtW6<<<6168, 256>>>(W_Qx, W_Kx, W_Vx, W_Ky, W_Vy, W_out,
                         b_Qx, b_Kx, b_Vx, b_Ky, b_Vy, b_out, W, biasC);

    cudaFuncSetAttribute(proj_tc,  cudaFuncAttributeMaxDynamicSharedMemorySize, GEMM_SMEM);
    cudaFuncSetAttribute(gemm_out, cudaFuncAttributeMaxDynamicSharedMemorySize, GEMM_SMEM);
    cudaFuncSetAttribute(attn_tc,  cudaFuncAttributeMaxDynamicSharedMemorySize, ATTN_SMEM);

    proj_tc<<<dim3(12, 32), 256, GEMM_SMEM>>>(xp, W, biasC, Qp, Kp, Vtp, 0);
    proj_tc<<<dim3(8, 32), 256, GEMM_SMEM>>>(yp, W + 3 * 1048576ull,
                                             biasC + 3 * 1024, Qp, Kp, Vtp, 1);

    attn_tc<<<dim3(4, 16, 4), 256, ATTN_SMEM>>>(Qp, Kp, Vtp, Op);

    gemm_out<<<dim3(4, 32), 256, GEMM_SMEM>>>(Op, W + 5 * 1048576ull, b_out, out);
}